// round 3
// baseline (speedup 1.0000x reference)
#include <cuda_runtime.h>
#include <cstdint>

#define N_NODES 50000
#define N_EDGES 800000
#define EN      (N_EDGES + N_NODES)   // edges + self loops

// ---------------- scratch (device globals; no allocation) ----------------
__device__ float g_h1[(size_t)N_NODES * 256];     // layer1 linear out [N,2,128]
__device__ float g_out1[(size_t)N_NODES * 256];   // layer1 GAT out (relu) [N,256]
__device__ float g_h2[(size_t)N_NODES * 128];     // layer2 linear out
__device__ float g_as1[N_NODES * 2];
__device__ float g_ad1[N_NODES * 2];
__device__ float g_as2[N_NODES];
__device__ float g_ad2[N_NODES];
__device__ float g_inv1[N_NODES * 2];
__device__ float g_inv2[N_NODES];
__device__ int   g_deg[N_NODES + 8];
__device__ int   g_off[N_NODES + 8];
__device__ int   g_cur[N_NODES + 8];
__device__ int   g_csr_src[EN];
__device__ float g_w1[(size_t)EN * 2];
__device__ float g_w2[EN];
__device__ int   g_is64;

// ---------------- edge dtype detection ----------------
// If edge_index is int64, values < 50000 => every odd 32-bit word is 0.
// If int32, odd words are src node ids, random in [0,50000): P(all 256 zero) ~ 0.
__global__ void detect_kernel(const int* __restrict__ ei_w) {
    int t = threadIdx.x;
    if (t == 0) g_is64 = 1;
    __syncthreads();
    if (ei_w[2 * t + 1] != 0) atomicAnd(&g_is64, 0);
}

__device__ __forceinline__ int load_edge(const void* ei, int is64, size_t idx) {
    if (is64) return (int)((const long long*)ei)[idx];
    return ((const int*)ei)[idx];
}

// ---------------- CSR build ----------------
__global__ void init_deg_kernel() {
    int i = blockIdx.x * blockDim.x + threadIdx.x;
    if (i < N_NODES) g_deg[i] = 1;  // self loop
}

__global__ void hist_kernel(const void* __restrict__ ei) {
    int e = blockIdx.x * blockDim.x + threadIdx.x;
    if (e < N_EDGES) {
        int dst = load_edge(ei, g_is64, (size_t)N_EDGES + e);
        atomicAdd(&g_deg[dst], 1);
    }
}

// single-block chunked exclusive scan over g_deg[0..N) -> g_off, g_cur; g_off[N]=EN
__global__ void scan_kernel() {
    __shared__ int warp_sums[32];
    __shared__ int s_carry;
    const int n = N_NODES;
    int t = threadIdx.x, lane = t & 31, wid = t >> 5;
    if (t == 0) s_carry = 0;
    __syncthreads();
    for (int base = 0; base < n; base += 1024) {
        int i = base + t;
        int v = (i < n) ? g_deg[i] : 0;
        int x = v;
        #pragma unroll
        for (int o = 1; o < 32; o <<= 1) {
            int y = __shfl_up_sync(0xffffffffu, x, o);
            if (lane >= o) x += y;
        }
        if (lane == 31) warp_sums[wid] = x;
        __syncthreads();
        if (wid == 0) {
            int ws = warp_sums[lane];
            #pragma unroll
            for (int o = 1; o < 32; o <<= 1) {
                int y = __shfl_up_sync(0xffffffffu, ws, o);
                if (lane >= o) ws += y;
            }
            warp_sums[lane] = ws;
        }
        __syncthreads();
        int excl = s_carry + x - v + (wid ? warp_sums[wid - 1] : 0);
        if (i < n) { g_off[i] = excl; g_cur[i] = excl; }
        __syncthreads();
        if (t == 1023) s_carry += warp_sums[31];
        __syncthreads();
    }
    if (t == 0) g_off[n] = EN;
}

__global__ void scatter_kernel(const void* __restrict__ ei) {
    int e = blockIdx.x * blockDim.x + threadIdx.x;
    if (e >= EN) return;
    int src, dst;
    if (e < N_EDGES) {
        int is64 = g_is64;
        src = load_edge(ei, is64, e);
        dst = load_edge(ei, is64, (size_t)N_EDGES + e);
    } else {
        src = e - N_EDGES; dst = src;
    }
    int pos = atomicAdd(&g_cur[dst], 1);
    g_csr_src[pos] = src;
}

// ---------------- SGEMM: C[m][n] = sum_k A[m][k] * B[n][k] ----------------
// LAYER=1: A = x (param), C = g_h1.  LAYER=2: A = g_out1, C = g_h2.
template <int LAYER>
__global__ __launch_bounds__(256) void sgemm_nt_kernel(
    const float* __restrict__ Aparam, const float* __restrict__ B,
    int M, int Nc, int K)
{
    const float* A = (LAYER == 1) ? Aparam : g_out1;
    float* C       = (LAYER == 1) ? g_h1   : g_h2;

    __shared__ float As[16][128 + 4];
    __shared__ float Bs[16][128 + 4];
    const int bm = blockIdx.x * 128;
    const int bn = blockIdx.y * 128;
    const int tid = threadIdx.x;
    const int tx = tid & 15, ty = tid >> 4;
    const int a_r = tid >> 2;
    const int a_c = (tid & 3) * 4;

    float acc[8][8];
    #pragma unroll
    for (int i = 0; i < 8; i++)
        #pragma unroll
        for (int j = 0; j < 8; j++) acc[i][j] = 0.f;

    for (int k0 = 0; k0 < K; k0 += 16) {
        #pragma unroll
        for (int i = 0; i < 2; i++) {
            int row = bm + a_r + i * 64;
            float4 v = make_float4(0.f, 0.f, 0.f, 0.f);
            if (row < M) v = *(const float4*)&A[(size_t)row * K + k0 + a_c];
            As[a_c + 0][a_r + i * 64] = v.x;
            As[a_c + 1][a_r + i * 64] = v.y;
            As[a_c + 2][a_r + i * 64] = v.z;
            As[a_c + 3][a_r + i * 64] = v.w;
        }
        #pragma unroll
        for (int i = 0; i < 2; i++) {
            int row = bn + a_r + i * 64;
            float4 v = make_float4(0.f, 0.f, 0.f, 0.f);
            if (row < Nc) v = *(const float4*)&B[(size_t)row * K + k0 + a_c];
            Bs[a_c + 0][a_r + i * 64] = v.x;
            Bs[a_c + 1][a_r + i * 64] = v.y;
            Bs[a_c + 2][a_r + i * 64] = v.z;
            Bs[a_c + 3][a_r + i * 64] = v.w;
        }
        __syncthreads();
        #pragma unroll
        for (int k = 0; k < 16; k++) {
            float ar[8], br[8];
            #pragma unroll
            for (int i = 0; i < 8; i++) ar[i] = As[k][ty * 8 + i];
            #pragma unroll
            for (int j = 0; j < 8; j++) br[j] = Bs[k][tx * 8 + j];
            #pragma unroll
            for (int i = 0; i < 8; i++)
                #pragma unroll
                for (int j = 0; j < 8; j++) acc[i][j] += ar[i] * br[j];
        }
        __syncthreads();
    }
    #pragma unroll
    for (int i = 0; i < 8; i++) {
        int row = bm + ty * 8 + i;
        if (row < M) {
            float* cp = &C[(size_t)row * Nc + bn + tx * 8];
            *(float4*)&cp[0] = make_float4(acc[i][0], acc[i][1], acc[i][2], acc[i][3]);
            *(float4*)&cp[4] = make_float4(acc[i][4], acc[i][5], acc[i][6], acc[i][7]);
        }
    }
}

// ---------------- per-node attention dots ----------------
template <int LAYER, int H, int C>
__global__ void attdot_kernel(const float* __restrict__ att_s,
                              const float* __restrict__ att_d)
{
    const float* h = (LAYER == 1) ? g_h1 : g_h2;
    float* a_s     = (LAYER == 1) ? g_as1 : g_as2;
    float* a_d     = (LAYER == 1) ? g_ad1 : g_ad2;

    int warp = (blockIdx.x * blockDim.x + threadIdx.x) >> 5;
    int lane = threadIdx.x & 31;
    if (warp >= N_NODES) return;
    const float* row = h + (size_t)warp * H * C;
    #pragma unroll
    for (int hh = 0; hh < H; hh++) {
        float ss = 0.f, sd = 0.f;
        for (int c = lane; c < C; c += 32) {
            float v = row[hh * C + c];
            ss += v * att_s[hh * C + c];
            sd += v * att_d[hh * C + c];
        }
        #pragma unroll
        for (int o = 16; o; o >>= 1) {
            ss += __shfl_xor_sync(0xffffffffu, ss, o);
            sd += __shfl_xor_sync(0xffffffffu, sd, o);
        }
        if (lane == 0) { a_s[warp * H + hh] = ss; a_d[warp * H + hh] = sd; }
    }
}

// ---------------- per-dst softmax stats (warp per node) ----------------
template <int LAYER, int H>
__global__ void edge_stats_kernel()
{
    const float* a_s = (LAYER == 1) ? g_as1 : g_as2;
    const float* a_d = (LAYER == 1) ? g_ad1 : g_ad2;
    float* w         = (LAYER == 1) ? g_w1  : g_w2;
    float* inv_      = (LAYER == 1) ? g_inv1 : g_inv2;

    int n = (blockIdx.x * blockDim.x + threadIdx.x) >> 5;
    int lane = threadIdx.x & 31;
    if (n >= N_NODES) return;
    int s0 = g_off[n], s1 = g_off[n + 1];
    float adv[H], mx[H], sm[H];
    #pragma unroll
    for (int h = 0; h < H; h++) { adv[h] = a_d[n * H + h]; mx[h] = -1e30f; sm[h] = 0.f; }
    for (int j = s0 + lane; j < s1; j += 32) {
        int src = g_csr_src[j];
        #pragma unroll
        for (int h = 0; h < H; h++) {
            float l = a_s[src * H + h] + adv[h];
            l = l > 0.f ? l : 0.2f * l;
            w[(size_t)j * H + h] = l;
            mx[h] = fmaxf(mx[h], l);
        }
    }
    #pragma unroll
    for (int h = 0; h < H; h++)
        #pragma unroll
        for (int o = 16; o; o >>= 1)
            mx[h] = fmaxf(mx[h], __shfl_xor_sync(0xffffffffu, mx[h], o));
    for (int j = s0 + lane; j < s1; j += 32) {
        #pragma unroll
        for (int h = 0; h < H; h++) {
            float e = __expf(w[(size_t)j * H + h] - mx[h]);
            w[(size_t)j * H + h] = e;
            sm[h] += e;
        }
    }
    #pragma unroll
    for (int h = 0; h < H; h++) {
        #pragma unroll
        for (int o = 16; o; o >>= 1)
            sm[h] += __shfl_xor_sync(0xffffffffu, sm[h], o);
        if (lane == 0) inv_[n * H + h] = 1.f / sm[h];
    }
}

// ---------------- gather aggregation (block per dst node) ----------------
template <int LAYER, int H, int C>
__global__ void aggregate_kernel(const float* __restrict__ bias,
                                 float* __restrict__ out_param)
{
    const float* hfeat = (LAYER == 1) ? g_h1  : g_h2;
    const float* w     = (LAYER == 1) ? g_w1  : g_w2;
    const float* inv_  = (LAYER == 1) ? g_inv1 : g_inv2;
    float* out         = (LAYER == 1) ? g_out1 : out_param;

    int n = blockIdx.x;
    int t = threadIdx.x;             // H*C threads
    int head = t / C;
    int s0 = g_off[n], s1 = g_off[n + 1];
    float acc = 0.f;
    int j = s0;
    for (; j + 1 < s1; j += 2) {
        int src0 = g_csr_src[j];
        int src1 = g_csr_src[j + 1];
        float w0 = w[(size_t)j * H + head];
        float w1 = w[(size_t)(j + 1) * H + head];
        float v0 = hfeat[(size_t)src0 * (H * C) + t];
        float v1 = hfeat[(size_t)src1 * (H * C) + t];
        acc += w0 * v0 + w1 * v1;
    }
    if (j < s1) {
        int src = g_csr_src[j];
        acc += w[(size_t)j * H + head] * hfeat[(size_t)src * (H * C) + t];
    }
    float v = acc * inv_[n * H + head] + bias[t];
    if (LAYER == 1) v = v > 0.f ? v : 0.f;
    out[(size_t)n * (H * C) + t] = v;
}

// ---------------- launch ----------------
extern "C" void kernel_launch(void* const* d_in, const int* in_sizes, int n_in,
                              void* d_out, int out_size)
{
    const float* x   = (const float*)d_in[0];
    const void*  ei  = d_in[1];                    // int32 or int64, detected on device
    const float* W1  = (const float*)d_in[2];
    const float* as1 = (const float*)d_in[3];
    const float* ad1 = (const float*)d_in[4];
    const float* b1  = (const float*)d_in[5];
    const float* W2  = (const float*)d_in[6];
    const float* as2 = (const float*)d_in[7];
    const float* ad2 = (const float*)d_in[8];
    const float* b2  = (const float*)d_in[9];
    float* out = (float*)d_out;

    // CSR build (dst-sorted adjacency, includes self loops)
    detect_kernel<<<1, 256>>>((const int*)ei);
    init_deg_kernel<<<(N_NODES + 255) / 256, 256>>>();
    hist_kernel<<<(N_EDGES + 255) / 256, 256>>>(ei);
    scan_kernel<<<1, 1024>>>();
    scatter_kernel<<<(EN + 255) / 256, 256>>>(ei);

    // Layer 1
    sgemm_nt_kernel<1><<<dim3((N_NODES + 127) / 128, 2), 256>>>(x, W1, N_NODES, 256, 256);
    attdot_kernel<1, 2, 128><<<(N_NODES + 7) / 8, 256>>>(as1, ad1);
    edge_stats_kernel<1, 2><<<(N_NODES + 7) / 8, 256>>>();
    aggregate_kernel<1, 2, 128><<<N_NODES, 256>>>(b1, nullptr);

    // Layer 2
    sgemm_nt_kernel<2><<<dim3((N_NODES + 127) / 128, 1), 256>>>(nullptr, W2, N_NODES, 128, 256);
    attdot_kernel<2, 1, 128><<<(N_NODES + 7) / 8, 256>>>(as2, ad2);
    edge_stats_kernel<2, 1><<<(N_NODES + 7) / 8, 256>>>();
    aggregate_kernel<2, 1, 128><<<N_NODES, 128>>>(b2, out);
}

// round 4
// speedup vs baseline: 1.3502x; 1.3502x over previous
#include <cuda_runtime.h>
#include <cuda_bf16.h>
#include <cstdint>

#define N_NODES 50000
#define N_EDGES 800000
#define EN      (N_EDGES + N_NODES)   // edges + self loops
#define NB      ((N_NODES + 255) / 256)   // scan blocks = 196

// ---------------- scratch (device globals; no allocation) ----------------
__device__ float g_h1[(size_t)N_NODES * 256];     // layer1 linear out [N,2,128]
__device__ float g_out1[(size_t)N_NODES * 256];   // layer1 GAT out (relu) [N,256]
__device__ float g_h2[(size_t)N_NODES * 128];     // layer2 linear out
__device__ float g_as1[N_NODES * 2];
__device__ float g_ad1[N_NODES * 2];
__device__ float g_as2[N_NODES];
__device__ float g_ad2[N_NODES];
__device__ float g_inv1[N_NODES * 2];
__device__ float g_inv2[N_NODES];
__device__ int   g_deg[N_NODES + 8];
__device__ int   g_off[N_NODES + 8];
__device__ int   g_cur[N_NODES + 8];
__device__ int   g_csr_src[EN];
__device__ float g_w1[(size_t)EN * 2];
__device__ float g_w2[EN];
__device__ int   g_is64;
__device__ int   g_bsum[NB + 8];
__device__ int   g_boff[NB + 8];

// ---------------- edge dtype detection ----------------
__global__ void detect_kernel(const int* __restrict__ ei_w) {
    int t = threadIdx.x;
    if (t == 0) g_is64 = 1;
    __syncthreads();
    if (ei_w[2 * t + 1] != 0) atomicAnd(&g_is64, 0);
}

__device__ __forceinline__ int load_edge(const void* ei, int is64, size_t idx) {
    if (is64) return (int)((const long long*)ei)[idx];
    return ((const int*)ei)[idx];
}

// ---------------- CSR build ----------------
__global__ void init_deg_kernel() {
    int i = blockIdx.x * blockDim.x + threadIdx.x;
    if (i < N_NODES) g_deg[i] = 1;  // self loop
}

__global__ void hist_kernel(const void* __restrict__ ei) {
    int e = blockIdx.x * blockDim.x + threadIdx.x;
    if (e < N_EDGES) {
        int dst = load_edge(ei, g_is64, (size_t)N_EDGES + e);
        atomicAdd(&g_deg[dst], 1);
    }
}

// phase 1: per-block inclusive scan; g_off[i] = inclusive-within-block, g_bsum[b]=block total
__global__ void scan1_kernel() {
    __shared__ int wsum[8];
    int b = blockIdx.x, t = threadIdx.x, lane = t & 31, wid = t >> 5;
    int i = b * 256 + t;
    int v = (i < N_NODES) ? g_deg[i] : 0;
    int x = v;
    #pragma unroll
    for (int o = 1; o < 32; o <<= 1) {
        int y = __shfl_up_sync(0xffffffffu, x, o);
        if (lane >= o) x += y;
    }
    if (lane == 31) wsum[wid] = x;
    __syncthreads();
    if (wid == 0 && lane < 8) {
        int ws = wsum[lane];
        #pragma unroll
        for (int o = 1; o < 8; o <<= 1) {
            int y = __shfl_up_sync(0xffu, ws, o);
            if (lane >= o) ws += y;
        }
        wsum[lane] = ws;
    }
    __syncthreads();
    int incl = x + (wid ? wsum[wid - 1] : 0);
    if (i < N_NODES) g_off[i] = incl;
    if (t == 255) g_bsum[b] = incl;
}

// phase 2: exclusive scan of NB block sums (single 256-thread block)
__global__ void scan2_kernel() {
    __shared__ int wsum[8];
    int t = threadIdx.x, lane = t & 31, wid = t >> 5;
    int v = (t < NB) ? g_bsum[t] : 0;
    int x = v;
    #pragma unroll
    for (int o = 1; o < 32; o <<= 1) {
        int y = __shfl_up_sync(0xffffffffu, x, o);
        if (lane >= o) x += y;
    }
    if (lane == 31) wsum[wid] = x;
    __syncthreads();
    if (wid == 0 && lane < 8) {
        int ws = wsum[lane];
        #pragma unroll
        for (int o = 1; o < 8; o <<= 1) {
            int y = __shfl_up_sync(0xffu, ws, o);
            if (lane >= o) ws += y;
        }
        wsum[lane] = ws;
    }
    __syncthreads();
    int excl = x - v + (wid ? wsum[wid - 1] : 0);
    if (t < NB) g_boff[t] = excl;
}

// phase 3: finalize exclusive offsets
__global__ void scan3_kernel() {
    int i = blockIdx.x * blockDim.x + threadIdx.x;
    if (i < N_NODES) {
        int e = g_off[i] - g_deg[i] + g_boff[blockIdx.x];
        g_off[i] = e;
        g_cur[i] = e;
    }
    if (i == 0) g_off[N_NODES] = EN;
}

__global__ void scatter_kernel(const void* __restrict__ ei) {
    int e = blockIdx.x * blockDim.x + threadIdx.x;
    if (e >= EN) return;
    int src, dst;
    if (e < N_EDGES) {
        int is64 = g_is64;
        src = load_edge(ei, is64, e);
        dst = load_edge(ei, is64, (size_t)N_EDGES + e);
    } else {
        src = e - N_EDGES; dst = src;
    }
    int pos = atomicAdd(&g_cur[dst], 1);
    g_csr_src[pos] = src;
}

// ================= bf16-split tensor-core GEMM =================
// C[m][n] = sum_k A[m][k]*B[n][k], fp32 in/out, K=256.
// Split a = ah + al (bf16). Tripled-K layout per 16-fp32 k-tile (48 bf16 cols):
//   seg0: A=hi B=hi | seg1: A=hi B=lo | seg2: A=lo B=hi
// smem rows = 128 bytes (64 bf16), SW128 swizzle, ldmatrix + mma.m16n8k16.bf16.
#define GBM 128
#define GBN 128
#define GKF 16      // fp32 k per tile

__device__ __forceinline__ uint32_t swz(uint32_t b) { return b ^ ((b >> 3) & 0x70); }

__device__ __forceinline__ uint32_t pack_bf2(__nv_bfloat16 lo, __nv_bfloat16 hi) {
    __nv_bfloat162 t(lo, hi);                 // lo -> low 16 bits (first in memory)
    return *reinterpret_cast<uint32_t*>(&t);
}

__device__ __forceinline__ void mma_bf16(float& c0, float& c1, float& c2, float& c3,
                                         uint32_t a0, uint32_t a1, uint32_t a2, uint32_t a3,
                                         uint32_t b0, uint32_t b1) {
    asm volatile(
        "mma.sync.aligned.m16n8k16.row.col.f32.bf16.bf16.f32 "
        "{%0,%1,%2,%3}, {%4,%5,%6,%7}, {%8,%9}, {%0,%1,%2,%3};\n"
        : "+f"(c0), "+f"(c1), "+f"(c2), "+f"(c3)
        : "r"(a0), "r"(a1), "r"(a2), "r"(a3), "r"(b0), "r"(b1));
}

template <int LAYER>
__global__ __launch_bounds__(256, 2) void gemm_bf16s_kernel(
    const float* __restrict__ Aparam, const float* __restrict__ B,
    int M, int Nc, int K)
{
    const float* A = (LAYER == 1) ? Aparam : g_out1;
    float* C       = (LAYER == 1) ? g_h1   : g_h2;

    __shared__ __align__(16) char sA[GBM * 128];
    __shared__ __align__(16) char sB[GBN * 128];
    uint32_t sAu = (uint32_t)__cvta_generic_to_shared(sA);
    uint32_t sBu = (uint32_t)__cvta_generic_to_shared(sB);

    const int tid = threadIdx.x;
    const int lane = tid & 31, wid = tid >> 5;
    const int wm = wid & 1, wn = wid >> 1;        // 2 x 4 warps, warp tile 64x32
    const int bm = blockIdx.x * GBM;
    const int bn = blockIdx.y * GBN;

    float acc[4][4][4];
    #pragma unroll
    for (int i = 0; i < 4; i++)
        #pragma unroll
        for (int j = 0; j < 4; j++)
            #pragma unroll
            for (int r = 0; r < 4; r++) acc[i][j][r] = 0.f;

    const int ldr = tid >> 2;       // 0..63
    const int quad = tid & 3;

    // ldmatrix lane address components (computed once)
    const int la_r   = lane & 7;
    const int la_sub = lane >> 3;               // 0..3 (A x4)
    const int lb_sub = (lane >> 3) & 1;         // B x2

    const int nktiles = K / GKF;                // 16
    for (int kt = 0; kt < nktiles; kt++) {
        // ---- load + split + swizzled store ----
        #pragma unroll
        for (int p = 0; p < 2; p++) {
            int r = ldr + p * 64;
            // A
            {
                int grow = bm + r;
                float4 v = make_float4(0.f, 0.f, 0.f, 0.f);
                if (grow < M) v = *(const float4*)&A[(size_t)grow * K + kt * GKF + quad * 4];
                __nv_bfloat16 h0 = __float2bfloat16(v.x), h1 = __float2bfloat16(v.y);
                __nv_bfloat16 h2 = __float2bfloat16(v.z), h3 = __float2bfloat16(v.w);
                __nv_bfloat16 l0 = __float2bfloat16(v.x - __bfloat162float(h0));
                __nv_bfloat16 l1 = __float2bfloat16(v.y - __bfloat162float(h1));
                __nv_bfloat16 l2 = __float2bfloat16(v.z - __bfloat162float(h2));
                __nv_bfloat16 l3 = __float2bfloat16(v.w - __bfloat162float(h3));
                uint2 hi = make_uint2(pack_bf2(h0, h1), pack_bf2(h2, h3));
                uint2 lo = make_uint2(pack_bf2(l0, l1), pack_bf2(l2, l3));
                uint32_t rb = (uint32_t)r * 128 + quad * 8;
                *(uint2*)(sA + swz(rb +  0)) = hi;   // seg0: hi
                *(uint2*)(sA + swz(rb + 32)) = hi;   // seg1: hi
                *(uint2*)(sA + swz(rb + 64)) = lo;   // seg2: lo
            }
            // B (rows always in-range: Nc >= GBN per launch config)
            {
                int grow = bn + r;
                float4 v = *(const float4*)&B[(size_t)grow * K + kt * GKF + quad * 4];
                __nv_bfloat16 h0 = __float2bfloat16(v.x), h1 = __float2bfloat16(v.y);
                __nv_bfloat16 h2 = __float2bfloat16(v.z), h3 = __float2bfloat16(v.w);
                __nv_bfloat16 l0 = __float2bfloat16(v.x - __bfloat162float(h0));
                __nv_bfloat16 l1 = __float2bfloat16(v.y - __bfloat162float(h1));
                __nv_bfloat16 l2 = __float2bfloat16(v.z - __bfloat162float(h2));
                __nv_bfloat16 l3 = __float2bfloat16(v.w - __bfloat162float(h3));
                uint2 hi = make_uint2(pack_bf2(h0, h1), pack_bf2(h2, h3));
                uint2 lo = make_uint2(pack_bf2(l0, l1), pack_bf2(l2, l3));
                uint32_t rb = (uint32_t)r * 128 + quad * 8;
                *(uint2*)(sB + swz(rb +  0)) = hi;   // seg0: hi
                *(uint2*)(sB + swz(rb + 32)) = lo;   // seg1: lo
                *(uint2*)(sB + swz(rb + 64)) = hi;   // seg2: hi
            }
        }
        __syncthreads();

        // ---- compute: 3 k-steps of 16 bf16 cols ----
        #pragma unroll
        for (int ks = 0; ks < 3; ks++) {
            uint32_t a[4][4], b[4][2];
            #pragma unroll
            for (int mt = 0; mt < 4; mt++) {
                int row = wm * 64 + mt * 16 + la_r + (la_sub & 1) * 8;
                uint32_t cb = (uint32_t)ks * 32 + (la_sub >> 1) * 16;
                uint32_t ad = sAu + swz((uint32_t)row * 128 + cb);
                asm volatile("ldmatrix.sync.aligned.m8n8.x4.shared.b16 {%0,%1,%2,%3}, [%4];"
                             : "=r"(a[mt][0]), "=r"(a[mt][1]), "=r"(a[mt][2]), "=r"(a[mt][3])
                             : "r"(ad));
            }
            #pragma unroll
            for (int nt = 0; nt < 4; nt++) {
                int row = wn * 32 + nt * 8 + la_r;
                uint32_t cb = (uint32_t)ks * 32 + lb_sub * 16;
                uint32_t ad = sBu + swz((uint32_t)row * 128 + cb);
                asm volatile("ldmatrix.sync.aligned.m8n8.x2.shared.b16 {%0,%1}, [%2];"
                             : "=r"(b[nt][0]), "=r"(b[nt][1])
                             : "r"(ad));
            }
            #pragma unroll
            for (int mt = 0; mt < 4; mt++)
                #pragma unroll
                for (int nt = 0; nt < 4; nt++)
                    mma_bf16(acc[mt][nt][0], acc[mt][nt][1], acc[mt][nt][2], acc[mt][nt][3],
                             a[mt][0], a[mt][1], a[mt][2], a[mt][3], b[nt][0], b[nt][1]);
        }
        __syncthreads();
    }

    // ---- epilogue ----
    const int g = lane >> 2, tg = lane & 3;
    #pragma unroll
    for (int mt = 0; mt < 4; mt++) {
        int r0 = bm + wm * 64 + mt * 16 + g;
        int r1 = r0 + 8;
        #pragma unroll
        for (int nt = 0; nt < 4; nt++) {
            int col = bn + wn * 32 + nt * 8 + tg * 2;
            if (r0 < M)
                *(float2*)&C[(size_t)r0 * Nc + col] = make_float2(acc[mt][nt][0], acc[mt][nt][1]);
            if (r1 < M)
                *(float2*)&C[(size_t)r1 * Nc + col] = make_float2(acc[mt][nt][2], acc[mt][nt][3]);
        }
    }
}

// ---------------- per-node attention dots ----------------
template <int LAYER, int H, int C>
__global__ void attdot_kernel(const float* __restrict__ att_s,
                              const float* __restrict__ att_d)
{
    const float* h = (LAYER == 1) ? g_h1 : g_h2;
    float* a_s     = (LAYER == 1) ? g_as1 : g_as2;
    float* a_d     = (LAYER == 1) ? g_ad1 : g_ad2;

    int warp = (blockIdx.x * blockDim.x + threadIdx.x) >> 5;
    int lane = threadIdx.x & 31;
    if (warp >= N_NODES) return;
    const float* row = h + (size_t)warp * H * C;
    #pragma unroll
    for (int hh = 0; hh < H; hh++) {
        float ss = 0.f, sd = 0.f;
        for (int c = lane; c < C; c += 32) {
            float v = row[hh * C + c];
            ss += v * att_s[hh * C + c];
            sd += v * att_d[hh * C + c];
        }
        #pragma unroll
        for (int o = 16; o; o >>= 1) {
            ss += __shfl_xor_sync(0xffffffffu, ss, o);
            sd += __shfl_xor_sync(0xffffffffu, sd, o);
        }
        if (lane == 0) { a_s[warp * H + hh] = ss; a_d[warp * H + hh] = sd; }
    }
}

// ---------------- per-dst softmax stats (warp per node) ----------------
template <int LAYER, int H>
__global__ void edge_stats_kernel()
{
    const float* a_s = (LAYER == 1) ? g_as1 : g_as2;
    const float* a_d = (LAYER == 1) ? g_ad1 : g_ad2;
    float* w         = (LAYER == 1) ? g_w1  : g_w2;
    float* inv_      = (LAYER == 1) ? g_inv1 : g_inv2;

    int n = (blockIdx.x * blockDim.x + threadIdx.x) >> 5;
    int lane = threadIdx.x & 31;
    if (n >= N_NODES) return;
    int s0 = g_off[n], s1 = g_off[n + 1];
    float adv[H], mx[H], sm[H];
    #pragma unroll
    for (int h = 0; h < H; h++) { adv[h] = a_d[n * H + h]; mx[h] = -1e30f; sm[h] = 0.f; }
    for (int j = s0 + lane; j < s1; j += 32) {
        int src = g_csr_src[j];
        #pragma unroll
        for (int h = 0; h < H; h++) {
            float l = a_s[src * H + h] + adv[h];
            l = l > 0.f ? l : 0.2f * l;
            w[(size_t)j * H + h] = l;
            mx[h] = fmaxf(mx[h], l);
        }
    }
    #pragma unroll
    for (int h = 0; h < H; h++)
        #pragma unroll
        for (int o = 16; o; o >>= 1)
            mx[h] = fmaxf(mx[h], __shfl_xor_sync(0xffffffffu, mx[h], o));
    for (int j = s0 + lane; j < s1; j += 32) {
        #pragma unroll
        for (int h = 0; h < H; h++) {
            float e = __expf(w[(size_t)j * H + h] - mx[h]);
            w[(size_t)j * H + h] = e;
            sm[h] += e;
        }
    }
    #pragma unroll
    for (int h = 0; h < H; h++) {
        #pragma unroll
        for (int o = 16; o; o >>= 1)
            sm[h] += __shfl_xor_sync(0xffffffffu, sm[h], o);
        if (lane == 0) inv_[n * H + h] = 1.f / sm[h];
    }
}

// ---------------- gather aggregation (block per dst node) ----------------
template <int LAYER, int H, int C>
__global__ void aggregate_kernel(const float* __restrict__ bias,
                                 float* __restrict__ out_param)
{
    const float* hfeat = (LAYER == 1) ? g_h1  : g_h2;
    const float* w     = (LAYER == 1) ? g_w1  : g_w2;
    const float* inv_  = (LAYER == 1) ? g_inv1 : g_inv2;
    float* out         = (LAYER == 1) ? g_out1 : out_param;

    int n = blockIdx.x;
    int t = threadIdx.x;             // H*C threads
    int head = t / C;
    int s0 = g_off[n], s1 = g_off[n + 1];
    float acc = 0.f;
    int j = s0;
    for (; j + 1 < s1; j += 2) {
        int src0 = g_csr_src[j];
        int src1 = g_csr_src[j + 1];
        float w0 = w[(size_t)j * H + head];
        float w1 = w[(size_t)(j + 1) * H + head];
        float v0 = hfeat[(size_t)src0 * (H * C) + t];
        float v1 = hfeat[(size_t)src1 * (H * C) + t];
        acc += w0 * v0 + w1 * v1;
    }
    if (j < s1) {
        int src = g_csr_src[j];
        acc += w[(size_t)j * H + head] * hfeat[(size_t)src * (H * C) + t];
    }
    float v = acc * inv_[n * H + head] + bias[t];
    if (LAYER == 1) v = v > 0.f ? v : 0.f;
    out[(size_t)n * (H * C) + t] = v;
}

// ---------------- launch ----------------
extern "C" void kernel_launch(void* const* d_in, const int* in_sizes, int n_in,
                              void* d_out, int out_size)
{
    const float* x   = (const float*)d_in[0];
    const void*  ei  = d_in[1];                    // int32 or int64, detected on device
    const float* W1  = (const float*)d_in[2];
    const float* as1 = (const float*)d_in[3];
    const float* ad1 = (const float*)d_in[4];
    const float* b1  = (const float*)d_in[5];
    const float* W2  = (const float*)d_in[6];
    const float* as2 = (const float*)d_in[7];
    const float* ad2 = (const float*)d_in[8];
    const float* b2  = (const float*)d_in[9];
    float* out = (float*)d_out;

    // CSR build (dst-sorted adjacency, includes self loops)
    detect_kernel<<<1, 256>>>((const int*)ei);
    init_deg_kernel<<<(N_NODES + 255) / 256, 256>>>();
    hist_kernel<<<(N_EDGES + 255) / 256, 256>>>(ei);
    scan1_kernel<<<NB, 256>>>();
    scan2_kernel<<<1, 256>>>();
    scan3_kernel<<<NB, 256>>>();
    scatter_kernel<<<(EN + 255) / 256, 256>>>(ei);

    // Layer 1
    gemm_bf16s_kernel<1><<<dim3((N_NODES + 127) / 128, 2), 256>>>(x, W1, N_NODES, 256, 256);
    attdot_kernel<1, 2, 128><<<(N_NODES + 7) / 8, 256>>>(as1, ad1);
    edge_stats_kernel<1, 2><<<(N_NODES + 7) / 8, 256>>>();
    aggregate_kernel<1, 2, 128><<<N_NODES, 256>>>(b1, nullptr);

    // Layer 2
    gemm_bf16s_kernel<2><<<dim3((N_NODES + 127) / 128, 1), 256>>>(nullptr, W2, N_NODES, 128, 256);
    attdot_kernel<2, 1, 128><<<(N_NODES + 7) / 8, 256>>>(as2, ad2);
    edge_stats_kernel<2, 1><<<(N_NODES + 7) / 8, 256>>>();
    aggregate_kernel<2, 1, 128><<<N_NODES, 128>>>(b2, out);
}

// round 5
// speedup vs baseline: 1.4467x; 1.0715x over previous
#include <cuda_runtime.h>
#include <cuda_bf16.h>
#include <cstdint>

#define N_NODES 50000
#define N_EDGES 800000
#define EN      (N_EDGES + N_NODES)   // edges + self loops
#define NB      ((N_NODES + 255) / 256)   // scan blocks = 196

// ---------------- scratch (device globals; no allocation) ----------------
__device__ float g_h1[(size_t)N_NODES * 256];     // layer1 linear out [N,2,128]
__device__ float g_out1[(size_t)N_NODES * 256];   // layer1 GAT out (relu) [N,256]
__device__ float g_h2[(size_t)N_NODES * 128];     // layer2 linear out
__device__ float g_as1[N_NODES * 2];
__device__ float g_ad1[N_NODES * 2];
__device__ float g_as2[N_NODES];
__device__ float g_ad2[N_NODES];
__device__ float g_inv1[N_NODES * 2];
__device__ float g_inv2[N_NODES];
__device__ int   g_deg[N_NODES + 8];
__device__ int   g_off[N_NODES + 8];
__device__ int   g_cur[N_NODES + 8];
__device__ int   g_csr_src[EN];
__device__ float g_w1[(size_t)EN * 2];
__device__ float g_w2[EN];
__device__ int   g_is64;
__device__ int   g_bsum[NB + 8];
__device__ int   g_boff[NB + 8];

// ---------------- edge dtype detection ----------------
__global__ void detect_kernel(const int* __restrict__ ei_w) {
    int t = threadIdx.x;
    if (t == 0) g_is64 = 1;
    __syncthreads();
    if (ei_w[2 * t + 1] != 0) atomicAnd(&g_is64, 0);
}

__device__ __forceinline__ int load_edge(const void* ei, int is64, size_t idx) {
    if (is64) return (int)((const long long*)ei)[idx];
    return ((const int*)ei)[idx];
}

// ---------------- CSR build ----------------
__global__ void init_deg_kernel() {
    int i = blockIdx.x * blockDim.x + threadIdx.x;
    if (i < N_NODES) g_deg[i] = 1;  // self loop
}

__global__ void hist_kernel(const void* __restrict__ ei) {
    int e = blockIdx.x * blockDim.x + threadIdx.x;
    if (e < N_EDGES) {
        int dst = load_edge(ei, g_is64, (size_t)N_EDGES + e);
        atomicAdd(&g_deg[dst], 1);
    }
}

// phase 1: per-block inclusive scan
__global__ void scan1_kernel() {
    __shared__ int wsum[8];
    int b = blockIdx.x, t = threadIdx.x, lane = t & 31, wid = t >> 5;
    int i = b * 256 + t;
    int v = (i < N_NODES) ? g_deg[i] : 0;
    int x = v;
    #pragma unroll
    for (int o = 1; o < 32; o <<= 1) {
        int y = __shfl_up_sync(0xffffffffu, x, o);
        if (lane >= o) x += y;
    }
    if (lane == 31) wsum[wid] = x;
    __syncthreads();
    if (wid == 0 && lane < 8) {
        int ws = wsum[lane];
        #pragma unroll
        for (int o = 1; o < 8; o <<= 1) {
            int y = __shfl_up_sync(0xffu, ws, o);
            if (lane >= o) ws += y;
        }
        wsum[lane] = ws;
    }
    __syncthreads();
    int incl = x + (wid ? wsum[wid - 1] : 0);
    if (i < N_NODES) g_off[i] = incl;
    if (t == 255) g_bsum[b] = incl;
}

// phase 2: exclusive scan of NB block sums
__global__ void scan2_kernel() {
    __shared__ int wsum[8];
    int t = threadIdx.x, lane = t & 31, wid = t >> 5;
    int v = (t < NB) ? g_bsum[t] : 0;
    int x = v;
    #pragma unroll
    for (int o = 1; o < 32; o <<= 1) {
        int y = __shfl_up_sync(0xffffffffu, x, o);
        if (lane >= o) x += y;
    }
    if (lane == 31) wsum[wid] = x;
    __syncthreads();
    if (wid == 0 && lane < 8) {
        int ws = wsum[lane];
        #pragma unroll
        for (int o = 1; o < 8; o <<= 1) {
            int y = __shfl_up_sync(0xffu, ws, o);
            if (lane >= o) ws += y;
        }
        wsum[lane] = ws;
    }
    __syncthreads();
    int excl = x - v + (wid ? wsum[wid - 1] : 0);
    if (t < NB) g_boff[t] = excl;
}

// phase 3: finalize exclusive offsets
__global__ void scan3_kernel() {
    int i = blockIdx.x * blockDim.x + threadIdx.x;
    if (i < N_NODES) {
        int e = g_off[i] - g_deg[i] + g_boff[blockIdx.x];
        g_off[i] = e;
        g_cur[i] = e;
    }
    if (i == 0) g_off[N_NODES] = EN;
}

__global__ void scatter_kernel(const void* __restrict__ ei) {
    int e = blockIdx.x * blockDim.x + threadIdx.x;
    if (e >= EN) return;
    int src, dst;
    if (e < N_EDGES) {
        int is64 = g_is64;
        src = load_edge(ei, is64, e);
        dst = load_edge(ei, is64, (size_t)N_EDGES + e);
    } else {
        src = e - N_EDGES; dst = src;
    }
    int pos = atomicAdd(&g_cur[dst], 1);
    g_csr_src[pos] = src;
}

// ================= bf16-split tensor-core GEMM (pipelined) =================
// C[m][n] = sum_k A[m][k]*B[n][k], fp32 in/out. Tripled-K bf16 split per
// 16-fp32 k-tile: seg0 A=hi,B=hi | seg1 A=hi,B=lo | seg2 A=lo,B=hi.
// Double-buffered smem + register-staged global prefetch; 1 sync / iter.
#define GBM 128
#define GBN 128
#define GKF 16
#define SBUF 16384

__device__ __forceinline__ uint32_t swz(uint32_t b) { return b ^ ((b >> 3) & 0x70); }

__device__ __forceinline__ uint32_t pack_bf2(__nv_bfloat16 lo, __nv_bfloat16 hi) {
    __nv_bfloat162 t(lo, hi);
    return *reinterpret_cast<uint32_t*>(&t);
}

__device__ __forceinline__ void cvt_split(float4 v, uint2& hi, uint2& lo) {
    __nv_bfloat16 h0 = __float2bfloat16(v.x), h1 = __float2bfloat16(v.y);
    __nv_bfloat16 h2 = __float2bfloat16(v.z), h3 = __float2bfloat16(v.w);
    __nv_bfloat16 l0 = __float2bfloat16(v.x - __bfloat162float(h0));
    __nv_bfloat16 l1 = __float2bfloat16(v.y - __bfloat162float(h1));
    __nv_bfloat16 l2 = __float2bfloat16(v.z - __bfloat162float(h2));
    __nv_bfloat16 l3 = __float2bfloat16(v.w - __bfloat162float(h3));
    hi = make_uint2(pack_bf2(h0, h1), pack_bf2(h2, h3));
    lo = make_uint2(pack_bf2(l0, l1), pack_bf2(l2, l3));
}

__device__ __forceinline__ void mma_bf16(float& c0, float& c1, float& c2, float& c3,
                                         uint32_t a0, uint32_t a1, uint32_t a2, uint32_t a3,
                                         uint32_t b0, uint32_t b1) {
    asm volatile(
        "mma.sync.aligned.m16n8k16.row.col.f32.bf16.bf16.f32 "
        "{%0,%1,%2,%3}, {%4,%5,%6,%7}, {%8,%9}, {%0,%1,%2,%3};\n"
        : "+f"(c0), "+f"(c1), "+f"(c2), "+f"(c3)
        : "r"(a0), "r"(a1), "r"(a2), "r"(a3), "r"(b0), "r"(b1));
}

template <int LAYER>
__global__ __launch_bounds__(256, 2) void gemm_bf16s_kernel(
    const float* __restrict__ Aparam, const float* __restrict__ B,
    int M, int Nc, int K)
{
    const float* A = (LAYER == 1) ? Aparam : g_out1;
    float* C       = (LAYER == 1) ? g_h1   : g_h2;

    __shared__ __align__(16) char sA[2 * SBUF];
    __shared__ __align__(16) char sB[2 * SBUF];
    uint32_t sAu = (uint32_t)__cvta_generic_to_shared(sA);
    uint32_t sBu = (uint32_t)__cvta_generic_to_shared(sB);

    const int tid = threadIdx.x;
    const int lane = tid & 31, wid = tid >> 5;
    const int wm = wid & 1, wn = wid >> 1;        // 2 x 4 warps, warp tile 64x32
    const int bm = blockIdx.x * GBM;
    const int bn = blockIdx.y * GBN;

    float acc[4][4][4];
    #pragma unroll
    for (int i = 0; i < 4; i++)
        #pragma unroll
        for (int j = 0; j < 4; j++)
            #pragma unroll
            for (int r = 0; r < 4; r++) acc[i][j][r] = 0.f;

    const int ldr = tid >> 2;       // 0..63
    const int quad = tid & 3;

    const int la_r   = lane & 7;
    const int la_sub = lane >> 3;
    const int lb_sub = (lane >> 3) & 1;

    uint2 stAh[2], stAl[2], stBh[2], stBl[2];

    auto load_tile = [&](int kt) {
        #pragma unroll
        for (int p = 0; p < 2; p++) {
            int r = ldr + p * 64;
            {
                int grow = bm + r;
                float4 v = make_float4(0.f, 0.f, 0.f, 0.f);
                if (grow < M) v = *(const float4*)&A[(size_t)grow * K + kt * GKF + quad * 4];
                cvt_split(v, stAh[p], stAl[p]);
            }
            {
                int grow = bn + r;
                float4 v = *(const float4*)&B[(size_t)grow * K + kt * GKF + quad * 4];
                cvt_split(v, stBh[p], stBl[p]);
            }
        }
    };
    auto store_tile = [&](int buf) {
        uint32_t bo = (uint32_t)buf * SBUF;
        #pragma unroll
        for (int p = 0; p < 2; p++) {
            int r = ldr + p * 64;
            uint32_t rb = (uint32_t)r * 128 + quad * 8;
            *(uint2*)(sA + bo + swz(rb +  0)) = stAh[p];
            *(uint2*)(sA + bo + swz(rb + 32)) = stAh[p];
            *(uint2*)(sA + bo + swz(rb + 64)) = stAl[p];
            *(uint2*)(sB + bo + swz(rb +  0)) = stBh[p];
            *(uint2*)(sB + bo + swz(rb + 32)) = stBl[p];
            *(uint2*)(sB + bo + swz(rb + 64)) = stBh[p];
        }
    };

    const int nktiles = K / GKF;
    load_tile(0);
    store_tile(0);
    __syncthreads();

    for (int kt = 0; kt < nktiles; kt++) {
        bool has_next = (kt + 1 < nktiles);
        if (has_next) load_tile(kt + 1);

        uint32_t bo = (uint32_t)(kt & 1) * SBUF;
        #pragma unroll
        for (int ks = 0; ks < 3; ks++) {
            uint32_t a[4][4], b[4][2];
            #pragma unroll
            for (int mt = 0; mt < 4; mt++) {
                int row = wm * 64 + mt * 16 + la_r + (la_sub & 1) * 8;
                uint32_t cb = (uint32_t)ks * 32 + (la_sub >> 1) * 16;
                uint32_t ad = sAu + bo + swz((uint32_t)row * 128 + cb);
                asm volatile("ldmatrix.sync.aligned.m8n8.x4.shared.b16 {%0,%1,%2,%3}, [%4];"
                             : "=r"(a[mt][0]), "=r"(a[mt][1]), "=r"(a[mt][2]), "=r"(a[mt][3])
                             : "r"(ad));
            }
            #pragma unroll
            for (int nt = 0; nt < 4; nt++) {
                int row = wn * 32 + nt * 8 + la_r;
                uint32_t cb = (uint32_t)ks * 32 + lb_sub * 16;
                uint32_t ad = sBu + bo + swz((uint32_t)row * 128 + cb);
                asm volatile("ldmatrix.sync.aligned.m8n8.x2.shared.b16 {%0,%1}, [%2];"
                             : "=r"(b[nt][0]), "=r"(b[nt][1])
                             : "r"(ad));
            }
            #pragma unroll
            for (int mt = 0; mt < 4; mt++)
                #pragma unroll
                for (int nt = 0; nt < 4; nt++)
                    mma_bf16(acc[mt][nt][0], acc[mt][nt][1], acc[mt][nt][2], acc[mt][nt][3],
                             a[mt][0], a[mt][1], a[mt][2], a[mt][3], b[nt][0], b[nt][1]);
        }
        if (has_next) {
            store_tile((kt + 1) & 1);
            __syncthreads();
        }
    }

    // ---- epilogue ----
    const int g = lane >> 2, tg = lane & 3;
    #pragma unroll
    for (int mt = 0; mt < 4; mt++) {
        int r0 = bm + wm * 64 + mt * 16 + g;
        int r1 = r0 + 8;
        #pragma unroll
        for (int nt = 0; nt < 4; nt++) {
            int col = bn + wn * 32 + nt * 8 + tg * 2;
            if (r0 < M)
                *(float2*)&C[(size_t)r0 * Nc + col] = make_float2(acc[mt][nt][0], acc[mt][nt][1]);
            if (r1 < M)
                *(float2*)&C[(size_t)r1 * Nc + col] = make_float2(acc[mt][nt][2], acc[mt][nt][3]);
        }
    }
}

// ---------------- per-node attention dots ----------------
template <int LAYER, int H, int C>
__global__ void attdot_kernel(const float* __restrict__ att_s,
                              const float* __restrict__ att_d)
{
    const float* h = (LAYER == 1) ? g_h1 : g_h2;
    float* a_s     = (LAYER == 1) ? g_as1 : g_as2;
    float* a_d     = (LAYER == 1) ? g_ad1 : g_ad2;

    int warp = (blockIdx.x * blockDim.x + threadIdx.x) >> 5;
    int lane = threadIdx.x & 31;
    if (warp >= N_NODES) return;
    const float* row = h + (size_t)warp * H * C;
    #pragma unroll
    for (int hh = 0; hh < H; hh++) {
        float ss = 0.f, sd = 0.f;
        for (int c = lane; c < C; c += 32) {
            float v = row[hh * C + c];
            ss += v * att_s[hh * C + c];
            sd += v * att_d[hh * C + c];
        }
        #pragma unroll
        for (int o = 16; o; o >>= 1) {
            ss += __shfl_xor_sync(0xffffffffu, ss, o);
            sd += __shfl_xor_sync(0xffffffffu, sd, o);
        }
        if (lane == 0) { a_s[warp * H + hh] = ss; a_d[warp * H + hh] = sd; }
    }
}

// ---------------- per-dst softmax stats (one pass, no max-sub) ----------------
// softmax is shift-invariant; logits are O(10) so exp is safe without max.
template <int LAYER, int H>
__global__ void edge_stats_kernel()
{
    const float* a_s = (LAYER == 1) ? g_as1 : g_as2;
    const float* a_d = (LAYER == 1) ? g_ad1 : g_ad2;
    float* w         = (LAYER == 1) ? g_w1  : g_w2;
    float* inv_      = (LAYER == 1) ? g_inv1 : g_inv2;

    int n = (blockIdx.x * blockDim.x + threadIdx.x) >> 5;
    int lane = threadIdx.x & 31;
    if (n >= N_NODES) return;
    int s0 = g_off[n], s1 = g_off[n + 1];
    float adv[H], sm[H];
    #pragma unroll
    for (int h = 0; h < H; h++) { adv[h] = a_d[n * H + h]; sm[h] = 0.f; }
    for (int j = s0 + lane; j < s1; j += 32) {
        int src = g_csr_src[j];
        #pragma unroll
        for (int h = 0; h < H; h++) {
            float l = a_s[src * H + h] + adv[h];
            l = l > 0.f ? l : 0.2f * l;
            float e = __expf(l);
            w[(size_t)j * H + h] = e;
            sm[h] += e;
        }
    }
    #pragma unroll
    for (int h = 0; h < H; h++) {
        #pragma unroll
        for (int o = 16; o; o >>= 1)
            sm[h] += __shfl_xor_sync(0xffffffffu, sm[h], o);
        if (lane == 0) inv_[n * H + h] = 1.f / sm[h];
    }
}

// ---------------- gather aggregation (block per dst node) ----------------
template <int LAYER, int H, int C>
__global__ void aggregate_kernel(const float* __restrict__ bias,
                                 float* __restrict__ out_param)
{
    const float* hfeat = (LAYER == 1) ? g_h1  : g_h2;
    const float* w     = (LAYER == 1) ? g_w1  : g_w2;
    const float* inv_  = (LAYER == 1) ? g_inv1 : g_inv2;
    float* out         = (LAYER == 1) ? g_out1 : out_param;

    int n = blockIdx.x;
    int t = threadIdx.x;             // H*C threads
    int head = t / C;
    int s0 = g_off[n], s1 = g_off[n + 1];
    float acc = 0.f;
    int j = s0;
    for (; j + 1 < s1; j += 2) {
        int src0 = g_csr_src[j];
        int src1 = g_csr_src[j + 1];
        float w0 = w[(size_t)j * H + head];
        float w1 = w[(size_t)(j + 1) * H + head];
        float v0 = hfeat[(size_t)src0 * (H * C) + t];
        float v1 = hfeat[(size_t)src1 * (H * C) + t];
        acc += w0 * v0 + w1 * v1;
    }
    if (j < s1) {
        int src = g_csr_src[j];
        acc += w[(size_t)j * H + head] * hfeat[(size_t)src * (H * C) + t];
    }
    float v = acc * inv_[n * H + head] + bias[t];
    if (LAYER == 1) v = v > 0.f ? v : 0.f;
    out[(size_t)n * (H * C) + t] = v;
}

// ---------------- launch ----------------
extern "C" void kernel_launch(void* const* d_in, const int* in_sizes, int n_in,
                              void* d_out, int out_size)
{
    const float* x   = (const float*)d_in[0];
    const void*  ei  = d_in[1];                    // int32 or int64, detected on device
    const float* W1  = (const float*)d_in[2];
    const float* as1 = (const float*)d_in[3];
    const float* ad1 = (const float*)d_in[4];
    const float* b1  = (const float*)d_in[5];
    const float* W2  = (const float*)d_in[6];
    const float* as2 = (const float*)d_in[7];
    const float* ad2 = (const float*)d_in[8];
    const float* b2  = (const float*)d_in[9];
    float* out = (float*)d_out;

    // CSR build (dst-sorted adjacency, includes self loops)
    detect_kernel<<<1, 256>>>((const int*)ei);
    init_deg_kernel<<<(N_NODES + 255) / 256, 256>>>();
    hist_kernel<<<(N_EDGES + 255) / 256, 256>>>(ei);
    scan1_kernel<<<NB, 256>>>();
    scan2_kernel<<<1, 256>>>();
    scan3_kernel<<<NB, 256>>>();
    scatter_kernel<<<(EN + 255) / 256, 256>>>(ei);

    // Layer 1
    gemm_bf16s_kernel<1><<<dim3((N_NODES + 127) / 128, 2), 256>>>(x, W1, N_NODES, 256, 256);
    attdot_kernel<1, 2, 128><<<(N_NODES + 7) / 8, 256>>>(as1, ad1);
    edge_stats_kernel<1, 2><<<(N_NODES + 7) / 8, 256>>>();
    aggregate_kernel<1, 2, 128><<<N_NODES, 256>>>(b1, nullptr);

    // Layer 2
    gemm_bf16s_kernel<2><<<dim3((N_NODES + 127) / 128, 1), 256>>>(nullptr, W2, N_NODES, 128, 256);
    attdot_kernel<2, 1, 128><<<(N_NODES + 7) / 8, 256>>>(as2, ad2);
    edge_stats_kernel<2, 1><<<(N_NODES + 7) / 8, 256>>>();
    aggregate_kernel<2, 1, 128><<<N_NODES, 128>>>(b2, out);
}

// round 6
// speedup vs baseline: 1.7205x; 1.1893x over previous
#include <cuda_runtime.h>
#include <cuda_bf16.h>
#include <cuda_fp16.h>
#include <cstdint>

#define N_NODES 50000
#define N_EDGES 800000
#define EN      (N_EDGES + N_NODES)   // edges + self loops
#define NB      ((N_NODES + 255) / 256)   // scan blocks = 196

// ---------------- scratch (device globals; no allocation) ----------------
__device__ float  g_h1[(size_t)N_NODES * 256];     // layer1 linear out [N,2,128]
__device__ float  g_out1[(size_t)N_NODES * 256];   // layer1 GAT out (relu) [N,256]
__device__ float  g_h2[(size_t)N_NODES * 128];     // layer2 linear out
__device__ __half g_h1h[(size_t)N_NODES * 256];    // fp16 gather copy of g_h1
__device__ __half g_h2h[(size_t)N_NODES * 128];    // fp16 gather copy of g_h2
__device__ float  g_as1[N_NODES * 2];
__device__ float  g_ad1[N_NODES * 2];
__device__ float  g_as2[N_NODES];
__device__ float  g_ad2[N_NODES];
__device__ float  g_inv1[N_NODES * 2];
__device__ float  g_inv2[N_NODES];
__device__ int    g_deg[N_NODES + 8];
__device__ int    g_off[N_NODES + 8];
__device__ int    g_cur[N_NODES + 8];
__device__ int    g_csr_src[EN];
__device__ float  g_w1[(size_t)EN * 2];
__device__ float  g_w2[EN];
__device__ int    g_is64;
__device__ int    g_bsum[NB + 8];
__device__ int    g_boff[NB + 8];

// ---------------- edge dtype detection ----------------
__global__ void detect_kernel(const int* __restrict__ ei_w) {
    int t = threadIdx.x;
    if (t == 0) g_is64 = 1;
    __syncthreads();
    if (ei_w[2 * t + 1] != 0) atomicAnd(&g_is64, 0);
}

__device__ __forceinline__ int load_edge(const void* ei, int is64, size_t idx) {
    if (is64) return (int)((const long long*)ei)[idx];
    return ((const int*)ei)[idx];
}

// ---------------- CSR build ----------------
__global__ void init_deg_kernel() {
    int i = blockIdx.x * blockDim.x + threadIdx.x;
    if (i < N_NODES) g_deg[i] = 1;  // self loop
}

__global__ void hist_kernel(const void* __restrict__ ei) {
    int e = blockIdx.x * blockDim.x + threadIdx.x;
    if (e < N_EDGES) {
        int dst = load_edge(ei, g_is64, (size_t)N_EDGES + e);
        atomicAdd(&g_deg[dst], 1);
    }
}

// phase 1: per-block inclusive scan
__global__ void scan1_kernel() {
    __shared__ int wsum[8];
    int b = blockIdx.x, t = threadIdx.x, lane = t & 31, wid = t >> 5;
    int i = b * 256 + t;
    int v = (i < N_NODES) ? g_deg[i] : 0;
    int x = v;
    #pragma unroll
    for (int o = 1; o < 32; o <<= 1) {
        int y = __shfl_up_sync(0xffffffffu, x, o);
        if (lane >= o) x += y;
    }
    if (lane == 31) wsum[wid] = x;
    __syncthreads();
    if (wid == 0 && lane < 8) {
        int ws = wsum[lane];
        #pragma unroll
        for (int o = 1; o < 8; o <<= 1) {
            int y = __shfl_up_sync(0xffu, ws, o);
            if (lane >= o) ws += y;
        }
        wsum[lane] = ws;
    }
    __syncthreads();
    int incl = x + (wid ? wsum[wid - 1] : 0);
    if (i < N_NODES) g_off[i] = incl;
    if (t == 255) g_bsum[b] = incl;
}

// phase 2: exclusive scan of NB block sums
__global__ void scan2_kernel() {
    __shared__ int wsum[8];
    int t = threadIdx.x, lane = t & 31, wid = t >> 5;
    int v = (t < NB) ? g_bsum[t] : 0;
    int x = v;
    #pragma unroll
    for (int o = 1; o < 32; o <<= 1) {
        int y = __shfl_up_sync(0xffffffffu, x, o);
        if (lane >= o) x += y;
    }
    if (lane == 31) wsum[wid] = x;
    __syncthreads();
    if (wid == 0 && lane < 8) {
        int ws = wsum[lane];
        #pragma unroll
        for (int o = 1; o < 8; o <<= 1) {
            int y = __shfl_up_sync(0xffu, ws, o);
            if (lane >= o) ws += y;
        }
        wsum[lane] = ws;
    }
    __syncthreads();
    int excl = x - v + (wid ? wsum[wid - 1] : 0);
    if (t < NB) g_boff[t] = excl;
}

// phase 3: finalize exclusive offsets
__global__ void scan3_kernel() {
    int i = blockIdx.x * blockDim.x + threadIdx.x;
    if (i < N_NODES) {
        int e = g_off[i] - g_deg[i] + g_boff[blockIdx.x];
        g_off[i] = e;
        g_cur[i] = e;
    }
    if (i == 0) g_off[N_NODES] = EN;
}

__global__ void scatter_kernel(const void* __restrict__ ei) {
    int e = blockIdx.x * blockDim.x + threadIdx.x;
    if (e >= EN) return;
    int src, dst;
    if (e < N_EDGES) {
        int is64 = g_is64;
        src = load_edge(ei, is64, e);
        dst = load_edge(ei, is64, (size_t)N_EDGES + e);
    } else {
        src = e - N_EDGES; dst = src;
    }
    int pos = atomicAdd(&g_cur[dst], 1);
    g_csr_src[pos] = src;
}

// ================= bf16-split tensor-core GEMM (pipelined) =================
#define GBM 128
#define GBN 128
#define GKF 16
#define SBUF 16384

__device__ __forceinline__ uint32_t swz(uint32_t b) { return b ^ ((b >> 3) & 0x70); }

__device__ __forceinline__ uint32_t pack_bf2(__nv_bfloat16 lo, __nv_bfloat16 hi) {
    __nv_bfloat162 t(lo, hi);
    return *reinterpret_cast<uint32_t*>(&t);
}

__device__ __forceinline__ void cvt_split(float4 v, uint2& hi, uint2& lo) {
    __nv_bfloat16 h0 = __float2bfloat16(v.x), h1 = __float2bfloat16(v.y);
    __nv_bfloat16 h2 = __float2bfloat16(v.z), h3 = __float2bfloat16(v.w);
    __nv_bfloat16 l0 = __float2bfloat16(v.x - __bfloat162float(h0));
    __nv_bfloat16 l1 = __float2bfloat16(v.y - __bfloat162float(h1));
    __nv_bfloat16 l2 = __float2bfloat16(v.z - __bfloat162float(h2));
    __nv_bfloat16 l3 = __float2bfloat16(v.w - __bfloat162float(h3));
    hi = make_uint2(pack_bf2(h0, h1), pack_bf2(h2, h3));
    lo = make_uint2(pack_bf2(l0, l1), pack_bf2(l2, l3));
}

__device__ __forceinline__ void mma_bf16(float& c0, float& c1, float& c2, float& c3,
                                         uint32_t a0, uint32_t a1, uint32_t a2, uint32_t a3,
                                         uint32_t b0, uint32_t b1) {
    asm volatile(
        "mma.sync.aligned.m16n8k16.row.col.f32.bf16.bf16.f32 "
        "{%0,%1,%2,%3}, {%4,%5,%6,%7}, {%8,%9}, {%0,%1,%2,%3};\n"
        : "+f"(c0), "+f"(c1), "+f"(c2), "+f"(c3)
        : "r"(a0), "r"(a1), "r"(a2), "r"(a3), "r"(b0), "r"(b1));
}

template <int LAYER>
__global__ __launch_bounds__(256, 2) void gemm_bf16s_kernel(
    const float* __restrict__ Aparam, const float* __restrict__ B,
    int M, int Nc, int K)
{
    const float* A = (LAYER == 1) ? Aparam : g_out1;
    float* C       = (LAYER == 1) ? g_h1   : g_h2;
    __half* Ch     = (LAYER == 1) ? g_h1h  : g_h2h;

    __shared__ __align__(16) char sA[2 * SBUF];
    __shared__ __align__(16) char sB[2 * SBUF];
    uint32_t sAu = (uint32_t)__cvta_generic_to_shared(sA);
    uint32_t sBu = (uint32_t)__cvta_generic_to_shared(sB);

    const int tid = threadIdx.x;
    const int lane = tid & 31, wid = tid >> 5;
    const int wm = wid & 1, wn = wid >> 1;        // 2 x 4 warps, warp tile 64x32
    const int bm = blockIdx.x * GBM;
    const int bn = blockIdx.y * GBN;

    float acc[4][4][4];
    #pragma unroll
    for (int i = 0; i < 4; i++)
        #pragma unroll
        for (int j = 0; j < 4; j++)
            #pragma unroll
            for (int r = 0; r < 4; r++) acc[i][j][r] = 0.f;

    const int ldr = tid >> 2;       // 0..63
    const int quad = tid & 3;

    const int la_r   = lane & 7;
    const int la_sub = lane >> 3;
    const int lb_sub = (lane >> 3) & 1;

    uint2 stAh[2], stAl[2], stBh[2], stBl[2];

    auto load_tile = [&](int kt) {
        #pragma unroll
        for (int p = 0; p < 2; p++) {
            int r = ldr + p * 64;
            {
                int grow = bm + r;
                float4 v = make_float4(0.f, 0.f, 0.f, 0.f);
                if (grow < M) v = *(const float4*)&A[(size_t)grow * K + kt * GKF + quad * 4];
                cvt_split(v, stAh[p], stAl[p]);
            }
            {
                int grow = bn + r;
                float4 v = *(const float4*)&B[(size_t)grow * K + kt * GKF + quad * 4];
                cvt_split(v, stBh[p], stBl[p]);
            }
        }
    };
    auto store_tile = [&](int buf) {
        uint32_t bo = (uint32_t)buf * SBUF;
        #pragma unroll
        for (int p = 0; p < 2; p++) {
            int r = ldr + p * 64;
            uint32_t rb = (uint32_t)r * 128 + quad * 8;
            *(uint2*)(sA + bo + swz(rb +  0)) = stAh[p];
            *(uint2*)(sA + bo + swz(rb + 32)) = stAh[p];
            *(uint2*)(sA + bo + swz(rb + 64)) = stAl[p];
            *(uint2*)(sB + bo + swz(rb +  0)) = stBh[p];
            *(uint2*)(sB + bo + swz(rb + 32)) = stBl[p];
            *(uint2*)(sB + bo + swz(rb + 64)) = stBh[p];
        }
    };

    const int nktiles = K / GKF;
    load_tile(0);
    store_tile(0);
    __syncthreads();

    for (int kt = 0; kt < nktiles; kt++) {
        bool has_next = (kt + 1 < nktiles);
        if (has_next) load_tile(kt + 1);

        uint32_t bo = (uint32_t)(kt & 1) * SBUF;
        #pragma unroll
        for (int ks = 0; ks < 3; ks++) {
            uint32_t a[4][4], b[4][2];
            #pragma unroll
            for (int mt = 0; mt < 4; mt++) {
                int row = wm * 64 + mt * 16 + la_r + (la_sub & 1) * 8;
                uint32_t cb = (uint32_t)ks * 32 + (la_sub >> 1) * 16;
                uint32_t ad = sAu + bo + swz((uint32_t)row * 128 + cb);
                asm volatile("ldmatrix.sync.aligned.m8n8.x4.shared.b16 {%0,%1,%2,%3}, [%4];"
                             : "=r"(a[mt][0]), "=r"(a[mt][1]), "=r"(a[mt][2]), "=r"(a[mt][3])
                             : "r"(ad));
            }
            #pragma unroll
            for (int nt = 0; nt < 4; nt++) {
                int row = wn * 32 + nt * 8 + la_r;
                uint32_t cb = (uint32_t)ks * 32 + lb_sub * 16;
                uint32_t ad = sBu + bo + swz((uint32_t)row * 128 + cb);
                asm volatile("ldmatrix.sync.aligned.m8n8.x2.shared.b16 {%0,%1}, [%2];"
                             : "=r"(b[nt][0]), "=r"(b[nt][1])
                             : "r"(ad));
            }
            #pragma unroll
            for (int mt = 0; mt < 4; mt++)
                #pragma unroll
                for (int nt = 0; nt < 4; nt++)
                    mma_bf16(acc[mt][nt][0], acc[mt][nt][1], acc[mt][nt][2], acc[mt][nt][3],
                             a[mt][0], a[mt][1], a[mt][2], a[mt][3], b[nt][0], b[nt][1]);
        }
        if (has_next) {
            store_tile((kt + 1) & 1);
            __syncthreads();
        }
    }

    // ---- epilogue: fp32 + fp16 copy ----
    const int g = lane >> 2, tg = lane & 3;
    #pragma unroll
    for (int mt = 0; mt < 4; mt++) {
        int r0 = bm + wm * 64 + mt * 16 + g;
        int r1 = r0 + 8;
        #pragma unroll
        for (int nt = 0; nt < 4; nt++) {
            int col = bn + wn * 32 + nt * 8 + tg * 2;
            if (r0 < M) {
                *(float2*)&C[(size_t)r0 * Nc + col] = make_float2(acc[mt][nt][0], acc[mt][nt][1]);
                *(__half2*)&Ch[(size_t)r0 * Nc + col] =
                    __floats2half2_rn(acc[mt][nt][0], acc[mt][nt][1]);
            }
            if (r1 < M) {
                *(float2*)&C[(size_t)r1 * Nc + col] = make_float2(acc[mt][nt][2], acc[mt][nt][3]);
                *(__half2*)&Ch[(size_t)r1 * Nc + col] =
                    __floats2half2_rn(acc[mt][nt][2], acc[mt][nt][3]);
            }
        }
    }
}

// ---------------- per-node attention dots ----------------
template <int LAYER, int H, int C>
__global__ void attdot_kernel(const float* __restrict__ att_s,
                              const float* __restrict__ att_d)
{
    const float* h = (LAYER == 1) ? g_h1 : g_h2;
    float* a_s     = (LAYER == 1) ? g_as1 : g_as2;
    float* a_d     = (LAYER == 1) ? g_ad1 : g_ad2;

    int warp = (blockIdx.x * blockDim.x + threadIdx.x) >> 5;
    int lane = threadIdx.x & 31;
    if (warp >= N_NODES) return;
    const float* row = h + (size_t)warp * H * C;
    #pragma unroll
    for (int hh = 0; hh < H; hh++) {
        float ss = 0.f, sd = 0.f;
        for (int c = lane; c < C; c += 32) {
            float v = row[hh * C + c];
            ss += v * att_s[hh * C + c];
            sd += v * att_d[hh * C + c];
        }
        #pragma unroll
        for (int o = 16; o; o >>= 1) {
            ss += __shfl_xor_sync(0xffffffffu, ss, o);
            sd += __shfl_xor_sync(0xffffffffu, sd, o);
        }
        if (lane == 0) { a_s[warp * H + hh] = ss; a_d[warp * H + hh] = sd; }
    }
}

// ---------------- per-dst softmax stats (one pass, no max-sub) ----------------
template <int LAYER, int H>
__global__ void edge_stats_kernel()
{
    const float* a_s = (LAYER == 1) ? g_as1 : g_as2;
    const float* a_d = (LAYER == 1) ? g_ad1 : g_ad2;
    float* w         = (LAYER == 1) ? g_w1  : g_w2;
    float* inv_      = (LAYER == 1) ? g_inv1 : g_inv2;

    int n = (blockIdx.x * blockDim.x + threadIdx.x) >> 5;
    int lane = threadIdx.x & 31;
    if (n >= N_NODES) return;
    int s0 = g_off[n], s1 = g_off[n + 1];
    float adv[H], sm[H];
    #pragma unroll
    for (int h = 0; h < H; h++) { adv[h] = a_d[n * H + h]; sm[h] = 0.f; }
    for (int j = s0 + lane; j < s1; j += 32) {
        int src = g_csr_src[j];
        #pragma unroll
        for (int h = 0; h < H; h++) {
            float l = a_s[src * H + h] + adv[h];
            l = l > 0.f ? l : 0.2f * l;
            float e = __expf(l);
            w[(size_t)j * H + h] = e;
            sm[h] += e;
        }
    }
    #pragma unroll
    for (int h = 0; h < H; h++) {
        #pragma unroll
        for (int o = 16; o; o >>= 1)
            sm[h] += __shfl_xor_sync(0xffffffffu, sm[h], o);
        if (lane == 0) inv_[n * H + h] = 1.f / sm[h];
    }
}

// ---------------- gather aggregation (block per dst node, fp16 rows) ----------------
// LAYER1: 128 threads, each handles feature pair (2t, 2t+1); head = t>>6.
// LAYER2: 64 threads,  each handles feature pair (2t, 2t+1); head = 0.
template <int LAYER, int H, int C>
__global__ void aggregate_kernel(const float* __restrict__ bias,
                                 float* __restrict__ out_param)
{
    const __half* hfeat = (LAYER == 1) ? g_h1h : g_h2h;
    const float* w      = (LAYER == 1) ? g_w1  : g_w2;
    const float* inv_   = (LAYER == 1) ? g_inv1 : g_inv2;
    float* out          = (LAYER == 1) ? g_out1 : out_param;

    const int HC = H * C;
    int n = blockIdx.x;
    int t = threadIdx.x;                 // HC/2 threads
    int f = 2 * t;                       // feature index (even)
    int head = f / C;
    int s0 = g_off[n], s1 = g_off[n + 1];
    float ax = 0.f, ay = 0.f;
    int j = s0;
    for (; j + 3 < s1; j += 4) {
        int src0 = g_csr_src[j + 0];
        int src1 = g_csr_src[j + 1];
        int src2 = g_csr_src[j + 2];
        int src3 = g_csr_src[j + 3];
        float w0 = w[(size_t)(j + 0) * H + head];
        float w1 = w[(size_t)(j + 1) * H + head];
        float w2 = w[(size_t)(j + 2) * H + head];
        float w3 = w[(size_t)(j + 3) * H + head];
        float2 v0 = __half22float2(*(const __half2*)&hfeat[(size_t)src0 * HC + f]);
        float2 v1 = __half22float2(*(const __half2*)&hfeat[(size_t)src1 * HC + f]);
        float2 v2 = __half22float2(*(const __half2*)&hfeat[(size_t)src2 * HC + f]);
        float2 v3 = __half22float2(*(const __half2*)&hfeat[(size_t)src3 * HC + f]);
        ax += w0 * v0.x + w1 * v1.x + w2 * v2.x + w3 * v3.x;
        ay += w0 * v0.y + w1 * v1.y + w2 * v2.y + w3 * v3.y;
    }
    for (; j < s1; j++) {
        int src = g_csr_src[j];
        float ww = w[(size_t)j * H + head];
        float2 v = __half22float2(*(const __half2*)&hfeat[(size_t)src * HC + f]);
        ax += ww * v.x;
        ay += ww * v.y;
    }
    float iv = inv_[n * H + head];
    float ox = ax * iv + bias[f];
    float oy = ay * iv + bias[f + 1];
    if (LAYER == 1) { ox = ox > 0.f ? ox : 0.f; oy = oy > 0.f ? oy : 0.f; }
    *(float2*)&out[(size_t)n * HC + f] = make_float2(ox, oy);
}

// ---------------- launch ----------------
extern "C" void kernel_launch(void* const* d_in, const int* in_sizes, int n_in,
                              void* d_out, int out_size)
{
    const float* x   = (const float*)d_in[0];
    const void*  ei  = d_in[1];                    // int32 or int64, detected on device
    const float* W1  = (const float*)d_in[2];
    const float* as1 = (const float*)d_in[3];
    const float* ad1 = (const float*)d_in[4];
    const float* b1  = (const float*)d_in[5];
    const float* W2  = (const float*)d_in[6];
    const float* as2 = (const float*)d_in[7];
    const float* ad2 = (const float*)d_in[8];
    const float* b2  = (const float*)d_in[9];
    float* out = (float*)d_out;

    // CSR build (dst-sorted adjacency, includes self loops)
    detect_kernel<<<1, 256>>>((const int*)ei);
    init_deg_kernel<<<(N_NODES + 255) / 256, 256>>>();
    hist_kernel<<<(N_EDGES + 255) / 256, 256>>>(ei);
    scan1_kernel<<<NB, 256>>>();
    scan2_kernel<<<1, 256>>>();
    scan3_kernel<<<NB, 256>>>();
    scatter_kernel<<<(EN + 255) / 256, 256>>>(ei);

    // Layer 1
    gemm_bf16s_kernel<1><<<dim3((N_NODES + 127) / 128, 2), 256>>>(x, W1, N_NODES, 256, 256);
    attdot_kernel<1, 2, 128><<<(N_NODES + 7) / 8, 256>>>(as1, ad1);
    edge_stats_kernel<1, 2><<<(N_NODES + 7) / 8, 256>>>();
    aggregate_kernel<1, 2, 128><<<N_NODES, 128>>>(b1, nullptr);

    // Layer 2
    gemm_bf16s_kernel<2><<<dim3((N_NODES + 127) / 128, 1), 256>>>(nullptr, W2, N_NODES, 128, 256);
    attdot_kernel<2, 1, 128><<<(N_NODES + 7) / 8, 256>>>(as2, ad2);
    edge_stats_kernel<2, 1><<<(N_NODES + 7) / 8, 256>>>();
    aggregate_kernel<2, 1, 128><<<N_NODES, 64>>>(b2, out);
}

// round 7
// speedup vs baseline: 1.9008x; 1.1047x over previous
#include <cuda_runtime.h>
#include <cuda_bf16.h>
#include <cuda_fp16.h>
#include <cstdint>

#define N_NODES 50000
#define N_EDGES 800000
#define EN      (N_EDGES + N_NODES)
#define NB      ((N_NODES + 255) / 256)

// ---------------- scratch (device globals; no allocation) ----------------
__device__ __nv_bfloat16 g_xh[(size_t)N_NODES * 256];
__device__ __nv_bfloat16 g_xl[(size_t)N_NODES * 256];
__device__ __nv_bfloat16 g_w1h[256 * 256], g_w1l[256 * 256];
__device__ __nv_bfloat16 g_w2h[128 * 256], g_w2l[128 * 256];
__device__ __nv_bfloat16 g_o1h[(size_t)N_NODES * 256];
__device__ __nv_bfloat16 g_o1l[(size_t)N_NODES * 256];
__device__ __half g_h1h[(size_t)N_NODES * 256];
__device__ __half g_h2h[(size_t)N_NODES * 128];
__device__ float  g_as1[N_NODES * 2];
__device__ float  g_ad1[N_NODES * 2];
__device__ float  g_as2[N_NODES];
__device__ float  g_ad2[N_NODES];
__device__ float  g_inv1[N_NODES * 2];
__device__ float  g_inv2[N_NODES];
__device__ int    g_deg[N_NODES + 8];
__device__ int    g_off[N_NODES + 8];
__device__ int    g_cur[N_NODES + 8];
__device__ int    g_csr_src[EN];
__device__ float  g_w1[(size_t)EN * 2];
__device__ float  g_w2[EN];
__device__ int    g_is64;
__device__ int    g_bsum[NB + 8];
__device__ int    g_boff[NB + 8];

// ---------------- helpers ----------------
__device__ __forceinline__ uint32_t swz(uint32_t b) { return b ^ ((b >> 3) & 0x70); }

__device__ __forceinline__ uint32_t pack_bf2(__nv_bfloat16 a, __nv_bfloat16 b) {
    __nv_bfloat162 t(a, b);
    return *reinterpret_cast<uint32_t*>(&t);
}

__device__ __forceinline__ void cp16(uint32_t dst, const void* src, int sz) {
    asm volatile("cp.async.cg.shared.global [%0], [%1], 16, %2;\n"
                 :: "r"(dst), "l"(src), "r"(sz) : "memory");
}
__device__ __forceinline__ void cp_commit() {
    asm volatile("cp.async.commit_group;\n" ::: "memory");
}
__device__ __forceinline__ void cp_wait1() {
    asm volatile("cp.async.wait_group 1;\n" ::: "memory");
}

__device__ __forceinline__ void mma_bf16(float& c0, float& c1, float& c2, float& c3,
                                         uint32_t a0, uint32_t a1, uint32_t a2, uint32_t a3,
                                         uint32_t b0, uint32_t b1) {
    asm volatile(
        "mma.sync.aligned.m16n8k16.row.col.f32.bf16.bf16.f32 "
        "{%0,%1,%2,%3}, {%4,%5,%6,%7}, {%8,%9}, {%0,%1,%2,%3};\n"
        : "+f"(c0), "+f"(c1), "+f"(c2), "+f"(c3)
        : "r"(a0), "r"(a1), "r"(a2), "r"(a3), "r"(b0), "r"(b1));
}

__device__ __forceinline__ void split4(float4 v, uint2& hi, uint2& lo) {
    __nv_bfloat16 h0 = __float2bfloat16(v.x), h1 = __float2bfloat16(v.y);
    __nv_bfloat16 h2 = __float2bfloat16(v.z), h3 = __float2bfloat16(v.w);
    __nv_bfloat16 l0 = __float2bfloat16(v.x - __bfloat162float(h0));
    __nv_bfloat16 l1 = __float2bfloat16(v.y - __bfloat162float(h1));
    __nv_bfloat16 l2 = __float2bfloat16(v.z - __bfloat162float(h2));
    __nv_bfloat16 l3 = __float2bfloat16(v.w - __bfloat162float(h3));
    hi = make_uint2(pack_bf2(h0, h1), pack_bf2(h2, h3));
    lo = make_uint2(pack_bf2(l0, l1), pack_bf2(l2, l3));
}

// ---------------- operand split kernels ----------------
__global__ void split_x_kernel(const float* __restrict__ src) {
    int i = blockIdx.x * blockDim.x + threadIdx.x;
    const int n4 = N_NODES * 256 / 4;
    if (i >= n4) return;
    uint2 hi, lo;
    split4(((const float4*)src)[i], hi, lo);
    ((uint2*)g_xh)[i] = hi;
    ((uint2*)g_xl)[i] = lo;
}

__global__ void split_w_kernel(const float* __restrict__ W1src,
                               const float* __restrict__ W2src) {
    int i = blockIdx.x * blockDim.x + threadIdx.x;
    const int n1 = 256 * 256 / 4;
    const int n2 = 128 * 256 / 4;
    if (i < n1) {
        uint2 hi, lo;
        split4(((const float4*)W1src)[i], hi, lo);
        ((uint2*)g_w1h)[i] = hi;
        ((uint2*)g_w1l)[i] = lo;
    } else if (i < n1 + n2) {
        int idx = i - n1;
        uint2 hi, lo;
        split4(((const float4*)W2src)[idx], hi, lo);
        ((uint2*)g_w2h)[idx] = hi;
        ((uint2*)g_w2l)[idx] = lo;
    }
}

// ---------------- CSR build ----------------
__global__ void init_kernel(const int* __restrict__ ei_w) {
    int i = blockIdx.x * blockDim.x + threadIdx.x;
    if (i < N_NODES) g_deg[i] = 1;  // self loop
    if (blockIdx.x == 0) {
        if (threadIdx.x == 0) g_is64 = 1;
        __syncthreads();
        if (ei_w[2 * threadIdx.x + 1] != 0) atomicAnd(&g_is64, 0);
    }
}

__device__ __forceinline__ int load_edge(const void* ei, int is64, size_t idx) {
    if (is64) return (int)((const long long*)ei)[idx];
    return ((const int*)ei)[idx];
}

__global__ void hist_kernel(const void* __restrict__ ei) {
    int e = blockIdx.x * blockDim.x + threadIdx.x;
    if (e < N_EDGES) {
        int dst = load_edge(ei, g_is64, (size_t)N_EDGES + e);
        atomicAdd(&g_deg[dst], 1);
    }
}

__global__ void scan1_kernel() {
    __shared__ int wsum[8];
    int b = blockIdx.x, t = threadIdx.x, lane = t & 31, wid = t >> 5;
    int i = b * 256 + t;
    int v = (i < N_NODES) ? g_deg[i] : 0;
    int x = v;
    #pragma unroll
    for (int o = 1; o < 32; o <<= 1) {
        int y = __shfl_up_sync(0xffffffffu, x, o);
        if (lane >= o) x += y;
    }
    if (lane == 31) wsum[wid] = x;
    __syncthreads();
    if (wid == 0 && lane < 8) {
        int ws = wsum[lane];
        #pragma unroll
        for (int o = 1; o < 8; o <<= 1) {
            int y = __shfl_up_sync(0xffu, ws, o);
            if (lane >= o) ws += y;
        }
        wsum[lane] = ws;
    }
    __syncthreads();
    int incl = x + (wid ? wsum[wid - 1] : 0);
    if (i < N_NODES) g_off[i] = incl;
    if (t == 255) g_bsum[b] = incl;
}

__global__ void scan2_kernel() {
    __shared__ int wsum[8];
    int t = threadIdx.x, lane = t & 31, wid = t >> 5;
    int v = (t < NB) ? g_bsum[t] : 0;
    int x = v;
    #pragma unroll
    for (int o = 1; o < 32; o <<= 1) {
        int y = __shfl_up_sync(0xffffffffu, x, o);
        if (lane >= o) x += y;
    }
    if (lane == 31) wsum[wid] = x;
    __syncthreads();
    if (wid == 0 && lane < 8) {
        int ws = wsum[lane];
        #pragma unroll
        for (int o = 1; o < 8; o <<= 1) {
            int y = __shfl_up_sync(0xffu, ws, o);
            if (lane >= o) ws += y;
        }
        wsum[lane] = ws;
    }
    __syncthreads();
    int excl = x - v + (wid ? wsum[wid - 1] : 0);
    if (t < NB) g_boff[t] = excl;
}

__global__ void scan3_kernel() {
    int i = blockIdx.x * blockDim.x + threadIdx.x;
    if (i < N_NODES) {
        int e = g_off[i] - g_deg[i] + g_boff[blockIdx.x];
        g_off[i] = e;
        g_cur[i] = e;
    }
    if (i == 0) g_off[N_NODES] = EN;
}

__global__ void scatter_kernel(const void* __restrict__ ei) {
    int e = blockIdx.x * blockDim.x + threadIdx.x;
    if (e >= EN) return;
    int src, dst;
    if (e < N_EDGES) {
        int is64 = g_is64;
        src = load_edge(ei, is64, e);
        dst = load_edge(ei, is64, (size_t)N_EDGES + e);
    } else {
        src = e - N_EDGES; dst = src;
    }
    int pos = atomicAdd(&g_cur[dst], 1);
    g_csr_src[pos] = src;
}

// ================= bf16-split GEMM, cp.async pipeline, fused attdot ==========
#define GBM 128
#define GBN 128
#define GKF 16
#define SBUF 16384
#define GEMM_K 256

template <int LAYER>
__global__ __launch_bounds__(256, 2) void gemm_kernel(
    int M, int Nc,
    const float* __restrict__ att_s_full, const float* __restrict__ att_d_full)
{
    const __nv_bfloat16* Ah = (LAYER == 1) ? g_xh  : g_o1h;
    const __nv_bfloat16* Al = (LAYER == 1) ? g_xl  : g_o1l;
    const __nv_bfloat16* Bh = (LAYER == 1) ? g_w1h : g_w2h;
    const __nv_bfloat16* Bl = (LAYER == 1) ? g_w1l : g_w2l;
    __half* Ch = (LAYER == 1) ? g_h1h : g_h2h;
    float* a_s = (LAYER == 1) ? g_as1 : g_as2;
    float* a_d = (LAYER == 1) ? g_ad1 : g_ad2;
    constexpr int H = (LAYER == 1) ? 2 : 1;

    __shared__ __align__(16) char sA[2 * SBUF];
    __shared__ __align__(16) char sB[2 * SBUF];
    uint32_t sAu = (uint32_t)__cvta_generic_to_shared(sA);
    uint32_t sBu = (uint32_t)__cvta_generic_to_shared(sB);

    const int tid = threadIdx.x;
    const int lane = tid & 31, wid = tid >> 5;
    const int wm = wid & 1, wn = wid >> 1;
    const int bm = blockIdx.x * GBM;
    const int bn = blockIdx.y * GBN;

    float acc[4][4][4];
    #pragma unroll
    for (int i = 0; i < 4; i++)
        #pragma unroll
        for (int j = 0; j < 4; j++)
            #pragma unroll
            for (int r = 0; r < 4; r++) acc[i][j][r] = 0.f;

    const int crow = tid >> 1;
    const int chalf = tid & 1;

    auto issue_tile = [&](int kt) {
        uint32_t bo = (uint32_t)(kt & 1) * SBUF;
        int k0 = kt * GKF;
        uint32_t rb = (uint32_t)crow * 128 + chalf * 16;
        {
            int grow = bm + crow;
            int sz = (grow < M) ? 16 : 0;
            const char* ph = (const char*)(Ah + (size_t)grow * GEMM_K + k0) + chalf * 16;
            const char* pl = (const char*)(Al + (size_t)grow * GEMM_K + k0) + chalf * 16;
            cp16(sAu + bo + swz(rb +  0), ph, sz);
            cp16(sAu + bo + swz(rb + 32), ph, sz);
            cp16(sAu + bo + swz(rb + 64), pl, sz);
        }
        {
            int gbrow = bn + crow;
            const char* ph = (const char*)(Bh + (size_t)gbrow * GEMM_K + k0) + chalf * 16;
            const char* pl = (const char*)(Bl + (size_t)gbrow * GEMM_K + k0) + chalf * 16;
            cp16(sBu + bo + swz(rb +  0), ph, 16);
            cp16(sBu + bo + swz(rb + 32), pl, 16);
            cp16(sBu + bo + swz(rb + 64), ph, 16);
        }
    };

    const int la_r   = lane & 7;
    const int la_sub = lane >> 3;
    const int lb_sub = (lane >> 3) & 1;

    const int nktiles = GEMM_K / GKF;
    issue_tile(0); cp_commit();
    issue_tile(1); cp_commit();

    for (int kt = 0; kt < nktiles; kt++) {
        cp_wait1();
        __syncthreads();
        uint32_t bo = (uint32_t)(kt & 1) * SBUF;
        #pragma unroll
        for (int ks = 0; ks < 3; ks++) {
            uint32_t a[4][4], b[4][2];
            #pragma unroll
            for (int mt = 0; mt < 4; mt++) {
                int row = wm * 64 + mt * 16 + la_r + (la_sub & 1) * 8;
                uint32_t cb = (uint32_t)ks * 32 + (la_sub >> 1) * 16;
                uint32_t ad = sAu + bo + swz((uint32_t)row * 128 + cb);
                asm volatile("ldmatrix.sync.aligned.m8n8.x4.shared.b16 {%0,%1,%2,%3}, [%4];"
                             : "=r"(a[mt][0]), "=r"(a[mt][1]), "=r"(a[mt][2]), "=r"(a[mt][3])
                             : "r"(ad));
            }
            #pragma unroll
            for (int nt = 0; nt < 4; nt++) {
                int row = wn * 32 + nt * 8 + la_r;
                uint32_t cb = (uint32_t)ks * 32 + lb_sub * 16;
                uint32_t ad = sBu + bo + swz((uint32_t)row * 128 + cb);
                asm volatile("ldmatrix.sync.aligned.m8n8.x2.shared.b16 {%0,%1}, [%2];"
                             : "=r"(b[nt][0]), "=r"(b[nt][1])
                             : "r"(ad));
            }
            #pragma unroll
            for (int mt = 0; mt < 4; mt++)
                #pragma unroll
                for (int nt = 0; nt < 4; nt++)
                    mma_bf16(acc[mt][nt][0], acc[mt][nt][1], acc[mt][nt][2], acc[mt][nt][3],
                             a[mt][0], a[mt][1], a[mt][2], a[mt][3], b[nt][0], b[nt][1]);
        }
        __syncthreads();
        if (kt + 2 < nktiles) issue_tile(kt + 2);
        cp_commit();
    }

    // ---- epilogue: fp16 C + fused attention dots ----
    const int g = lane >> 2, tg = lane & 3;

    #pragma unroll
    for (int mt = 0; mt < 4; mt++) {
        int r0 = bm + wm * 64 + mt * 16 + g;
        int r1 = r0 + 8;
        #pragma unroll
        for (int nt = 0; nt < 4; nt++) {
            int col = bn + wn * 32 + nt * 8 + tg * 2;
            if (r0 < M)
                *(__half2*)&Ch[(size_t)r0 * Nc + col] =
                    __floats2half2_rn(acc[mt][nt][0], acc[mt][nt][1]);
            if (r1 < M)
                *(__half2*)&Ch[(size_t)r1 * Nc + col] =
                    __floats2half2_rn(acc[mt][nt][2], acc[mt][nt][3]);
        }
    }

    float2 asv[4], adv[4];
    #pragma unroll
    for (int nt = 0; nt < 4; nt++) {
        int col = bn + wn * 32 + nt * 8 + tg * 2;
        asv[nt] = *(const float2*)&att_s_full[col];
        adv[nt] = *(const float2*)&att_d_full[col];
    }
    float ssr0[4], ssr1[4], sdr0[4], sdr1[4];
    #pragma unroll
    for (int mt = 0; mt < 4; mt++) {
        float s0 = 0.f, s1 = 0.f, d0 = 0.f, d1 = 0.f;
        #pragma unroll
        for (int nt = 0; nt < 4; nt++) {
            s0 += asv[nt].x * acc[mt][nt][0] + asv[nt].y * acc[mt][nt][1];
            s1 += asv[nt].x * acc[mt][nt][2] + asv[nt].y * acc[mt][nt][3];
            d0 += adv[nt].x * acc[mt][nt][0] + adv[nt].y * acc[mt][nt][1];
            d1 += adv[nt].x * acc[mt][nt][2] + adv[nt].y * acc[mt][nt][3];
        }
        #pragma unroll
        for (int o = 1; o <= 2; o <<= 1) {
            s0 += __shfl_xor_sync(0xffffffffu, s0, o);
            s1 += __shfl_xor_sync(0xffffffffu, s1, o);
            d0 += __shfl_xor_sync(0xffffffffu, d0, o);
            d1 += __shfl_xor_sync(0xffffffffu, d1, o);
        }
        ssr0[mt] = s0; ssr1[mt] = s1; sdr0[mt] = d0; sdr1[mt] = d1;
    }
    __syncthreads();
    float* red = (float*)sA;
    if (tg == 0) {
        #pragma unroll
        for (int mt = 0; mt < 4; mt++) {
            int rl0 = wm * 64 + mt * 16 + g;
            red[wn * 128 + rl0]           = ssr0[mt];
            red[wn * 128 + rl0 + 8]       = ssr1[mt];
            red[512 + wn * 128 + rl0]     = sdr0[mt];
            red[512 + wn * 128 + rl0 + 8] = sdr1[mt];
        }
    }
    __syncthreads();
    if (tid < 128) {
        int row = tid;
        float ss = red[row] + red[128 + row] + red[256 + row] + red[384 + row];
        float sd = red[512 + row] + red[640 + row] + red[768 + row] + red[896 + row];
        int grow = bm + row;
        if (grow < M) {
            int head = (H == 2) ? (int)blockIdx.y : 0;
            a_s[grow * H + head] = ss;
            a_d[grow * H + head] = sd;
        }
    }
}

// ---------------- per-dst softmax stats (one pass) ----------------
template <int LAYER, int H>
__global__ void edge_stats_kernel()
{
    const float* a_s = (LAYER == 1) ? g_as1 : g_as2;
    const float* a_d = (LAYER == 1) ? g_ad1 : g_ad2;
    float* w         = (LAYER == 1) ? g_w1  : g_w2;
    float* inv_      = (LAYER == 1) ? g_inv1 : g_inv2;

    int n = (blockIdx.x * blockDim.x + threadIdx.x) >> 5;
    int lane = threadIdx.x & 31;
    if (n >= N_NODES) return;
    int s0 = g_off[n], s1 = g_off[n + 1];
    float adv[H], sm[H];
    #pragma unroll
    for (int h = 0; h < H; h++) { adv[h] = a_d[n * H + h]; sm[h] = 0.f; }
    for (int j = s0 + lane; j < s1; j += 32) {
        int src = g_csr_src[j];
        #pragma unroll
        for (int h = 0; h < H; h++) {
            float l = a_s[src * H + h] + adv[h];
            l = l > 0.f ? l : 0.2f * l;
            float e = __expf(l);
            w[(size_t)j * H + h] = e;
            sm[h] += e;
        }
    }
    #pragma unroll
    for (int h = 0; h < H; h++) {
        #pragma unroll
        for (int o = 16; o; o >>= 1)
            sm[h] += __shfl_xor_sync(0xffffffffu, sm[h], o);
        if (lane == 0) inv_[n * H + h] = 1.f / sm[h];
    }
}

// ---------------- gather aggregation (block per dst node, fp16 rows) ----------------
template <int LAYER, int H, int C>
__global__ void aggregate_kernel(const float* __restrict__ bias,
                                 float* __restrict__ out_param)
{
    const __half* hfeat = (LAYER == 1) ? g_h1h : g_h2h;
    const float* w      = (LAYER == 1) ? g_w1  : g_w2;
    const float* inv_   = (LAYER == 1) ? g_inv1 : g_inv2;

    const int HC = H * C;
    int n = blockIdx.x;
    int t = threadIdx.x;
    int f = 2 * t;
    int head = f / C;
    int s0 = g_off[n], s1 = g_off[n + 1];
    float ax = 0.f, ay = 0.f;
    int j = s0;
    for (; j + 3 < s1; j += 4) {
        int src0 = g_csr_src[j + 0];
        int src1 = g_csr_src[j + 1];
        int src2 = g_csr_src[j + 2];
        int src3 = g_csr_src[j + 3];
        float w0 = w[(size_t)(j + 0) * H + head];
        float w1 = w[(size_t)(j + 1) * H + head];
        float w2 = w[(size_t)(j + 2) * H + head];
        float w3 = w[(size_t)(j + 3) * H + head];
        float2 v0 = __half22float2(*(const __half2*)&hfeat[(size_t)src0 * HC + f]);
        float2 v1 = __half22float2(*(const __half2*)&hfeat[(size_t)src1 * HC + f]);
        float2 v2 = __half22float2(*(const __half2*)&hfeat[(size_t)src2 * HC + f]);
        float2 v3 = __half22float2(*(const __half2*)&hfeat[(size_t)src3 * HC + f]);
        ax += w0 * v0.x + w1 * v1.x + w2 * v2.x + w3 * v3.x;
        ay += w0 * v0.y + w1 * v1.y + w2 * v2.y + w3 * v3.y;
    }
    for (; j < s1; j++) {
        int src = g_csr_src[j];
        float ww = w[(size_t)j * H + head];
        float2 v = __half22float2(*(const __half2*)&hfeat[(size_t)src * HC + f]);
        ax += ww * v.x;
        ay += ww * v.y;
    }
    float iv = inv_[n * H + head];
    float ox = ax * iv + bias[f];
    float oy = ay * iv + bias[f + 1];
    if (LAYER == 1) {
        ox = ox > 0.f ? ox : 0.f;
        oy = oy > 0.f ? oy : 0.f;
        __nv_bfloat16 hx = __float2bfloat16(ox), hy = __float2bfloat16(oy);
        __nv_bfloat16 lx = __float2bfloat16(ox - __bfloat162float(hx));
        __nv_bfloat16 ly = __float2bfloat16(oy - __bfloat162float(hy));
        __nv_bfloat162 hv; hv.x = hx; hv.y = hy;
        __nv_bfloat162 lv; lv.x = lx; lv.y = ly;
        *(__nv_bfloat162*)&g_o1h[(size_t)n * HC + f] = hv;
        *(__nv_bfloat162*)&g_o1l[(size_t)n * HC + f] = lv;
    } else {
        *(float2*)&out_param[(size_t)n * HC + f] = make_float2(ox, oy);
    }
}

// ---------------- launch ----------------
extern "C" void kernel_launch(void* const* d_in, const int* in_sizes, int n_in,
                              void* d_out, int out_size)
{
    const float* x   = (const float*)d_in[0];
    const void*  ei  = d_in[1];
    const float* W1  = (const float*)d_in[2];
    const float* as1 = (const float*)d_in[3];
    const float* ad1 = (const float*)d_in[4];
    const float* b1  = (const float*)d_in[5];
    const float* W2  = (const float*)d_in[6];
    const float* as2 = (const float*)d_in[7];
    const float* ad2 = (const float*)d_in[8];
    const float* b2  = (const float*)d_in[9];
    float* out = (float*)d_out;

    // operand splits
    split_x_kernel<<<(N_NODES * 256 / 4 + 255) / 256, 256>>>(x);
    split_w_kernel<<<((256 * 256 + 128 * 256) / 4 + 255) / 256, 256>>>(W1, W2);

    // CSR build
    init_kernel<<<NB, 256>>>((const int*)ei);
    hist_kernel<<<(N_EDGES + 255) / 256, 256>>>(ei);
    scan1_kernel<<<NB, 256>>>();
    scan2_kernel<<<1, 256>>>();
    scan3_kernel<<<NB, 256>>>();
    scatter_kernel<<<(EN + 255) / 256, 256>>>(ei);

    // Layer 1
    gemm_kernel<1><<<dim3((N_NODES + 127) / 128, 2), 256>>>(N_NODES, 256, as1, ad1);
    edge_stats_kernel<1, 2><<<(N_NODES + 7) / 8, 256>>>();
    aggregate_kernel<1, 2, 128><<<N_NODES, 128>>>(b1, nullptr);

    // Layer 2
    gemm_kernel<2><<<dim3((N_NODES + 127) / 128, 1), 256>>>(N_NODES, 128, as2, ad2);
    edge_stats_kernel<2, 1><<<(N_NODES + 7) / 8, 256>>>();
    aggregate_kernel<2, 1, 128><<<N_NODES, 64>>>(b2, out);
}

// round 9
// speedup vs baseline: 2.2952x; 1.2075x over previous
#include <cuda_runtime.h>
#include <cuda_bf16.h>
#include <cuda_fp16.h>
#include <cstdint>

#define N_NODES 50000
#define N_EDGES 800000
#define EN      (N_EDGES + N_NODES)
#define NB      ((N_NODES + 255) / 256)

// ---------------- scratch (device globals; no allocation) ----------------
__device__ __half g_xh[(size_t)N_NODES * 256];   // x split hi (fp16)
__device__ __half g_xl[(size_t)N_NODES * 256];   // x split lo (fp16)
__device__ __half g_w1h[256 * 256];              // W1 fp16
__device__ __half g_w2h[128 * 256];              // W2 fp16
__device__ __half g_o1h[(size_t)N_NODES * 256];  // layer1 out split hi
__device__ __half g_o1l[(size_t)N_NODES * 256];  // layer1 out split lo
__device__ __half g_h1h[(size_t)N_NODES * 256];  // fp16 gather copy (layer1 lin)
__device__ __half g_h2h[(size_t)N_NODES * 128];  // fp16 gather copy (layer2 lin)
__device__ float  g_as1[N_NODES * 2];
__device__ float  g_ad1[N_NODES * 2];
__device__ float  g_as2[N_NODES];
__device__ float  g_ad2[N_NODES];
__device__ int    g_deg[N_NODES + 8];
__device__ int    g_off[N_NODES + 8];
__device__ int    g_cur[N_NODES + 8];
__device__ int    g_csr_src[EN];
__device__ int    g_is64;
__device__ int    g_bsum[NB + 8];
__device__ int    g_boff[NB + 8];

// ---------------- helpers ----------------
__device__ __forceinline__ uint32_t swz(uint32_t b) { return b ^ ((b >> 3) & 0x70); }

__device__ __forceinline__ uint32_t pack_h2(__half a, __half b) {
    __half2 t(a, b);
    return *reinterpret_cast<uint32_t*>(&t);
}

__device__ __forceinline__ void cp16(uint32_t dst, const void* src, int sz) {
    asm volatile("cp.async.cg.shared.global [%0], [%1], 16, %2;\n"
                 :: "r"(dst), "l"(src), "r"(sz) : "memory");
}
__device__ __forceinline__ void cp_commit() {
    asm volatile("cp.async.commit_group;\n" ::: "memory");
}
__device__ __forceinline__ void cp_wait1() {
    asm volatile("cp.async.wait_group 1;\n" ::: "memory");
}

__device__ __forceinline__ void mma_fp16(float& c0, float& c1, float& c2, float& c3,
                                         uint32_t a0, uint32_t a1, uint32_t a2, uint32_t a3,
                                         uint32_t b0, uint32_t b1) {
    asm volatile(
        "mma.sync.aligned.m16n8k16.row.col.f32.f16.f16.f32 "
        "{%0,%1,%2,%3}, {%4,%5,%6,%7}, {%8,%9}, {%0,%1,%2,%3};\n"
        : "+f"(c0), "+f"(c1), "+f"(c2), "+f"(c3)
        : "r"(a0), "r"(a1), "r"(a2), "r"(a3), "r"(b0), "r"(b1));
}

__device__ __forceinline__ void split4h(float4 v, uint2& hi, uint2& lo) {
    __half h0 = __float2half_rn(v.x), h1 = __float2half_rn(v.y);
    __half h2 = __float2half_rn(v.z), h3 = __float2half_rn(v.w);
    __half l0 = __float2half_rn(v.x - __half2float(h0));
    __half l1 = __float2half_rn(v.y - __half2float(h1));
    __half l2 = __float2half_rn(v.z - __half2float(h2));
    __half l3 = __float2half_rn(v.w - __half2float(h3));
    hi = make_uint2(pack_h2(h0, h1), pack_h2(h2, h3));
    lo = make_uint2(pack_h2(l0, l1), pack_h2(l2, l3));
}

// ---------------- operand split kernels ----------------
__global__ void split_x_kernel(const float* __restrict__ src) {
    int i = blockIdx.x * blockDim.x + threadIdx.x;
    const int n4 = N_NODES * 256 / 4;
    if (i >= n4) return;
    uint2 hi, lo;
    split4h(((const float4*)src)[i], hi, lo);
    ((uint2*)g_xh)[i] = hi;
    ((uint2*)g_xl)[i] = lo;
}

__global__ void split_w_kernel(const float* __restrict__ W1src,
                               const float* __restrict__ W2src) {
    int i = blockIdx.x * blockDim.x + threadIdx.x;
    const int n1 = 256 * 256 / 4;
    const int n2 = 128 * 256 / 4;
    const float* src;
    uint2* dh;
    int idx;
    if (i < n1) { src = W1src; dh = (uint2*)g_w1h; idx = i; }
    else if (i < n1 + n2) { src = W2src; dh = (uint2*)g_w2h; idx = i - n1; }
    else return;
    float4 v = ((const float4*)src)[idx];
    __half h0 = __float2half_rn(v.x), h1 = __float2half_rn(v.y);
    __half h2 = __float2half_rn(v.z), h3 = __float2half_rn(v.w);
    dh[idx] = make_uint2(pack_h2(h0, h1), pack_h2(h2, h3));
}

// ---------------- CSR build ----------------
__global__ void init_kernel(const int* __restrict__ ei_w) {
    int i = blockIdx.x * blockDim.x + threadIdx.x;
    if (i < N_NODES) g_deg[i] = 1;
    if (blockIdx.x == 0) {
        if (threadIdx.x == 0) g_is64 = 1;
        __syncthreads();
        if (ei_w[2 * threadIdx.x + 1] != 0) atomicAnd(&g_is64, 0);
    }
}

__device__ __forceinline__ int load_edge(const void* ei, int is64, size_t idx) {
    if (is64) return (int)((const long long*)ei)[idx];
    return ((const int*)ei)[idx];
}

__global__ void hist_kernel(const void* __restrict__ ei) {
    int e = blockIdx.x * blockDim.x + threadIdx.x;
    if (e < N_EDGES) {
        int dst = load_edge(ei, g_is64, (size_t)N_EDGES + e);
        atomicAdd(&g_deg[dst], 1);
    }
}

__global__ void scan1_kernel() {
    __shared__ int wsum[8];
    int b = blockIdx.x, t = threadIdx.x, lane = t & 31, wid = t >> 5;
    int i = b * 256 + t;
    int v = (i < N_NODES) ? g_deg[i] : 0;
    int x = v;
    #pragma unroll
    for (int o = 1; o < 32; o <<= 1) {
        int y = __shfl_up_sync(0xffffffffu, x, o);
        if (lane >= o) x += y;
    }
    if (lane == 31) wsum[wid] = x;
    __syncthreads();
    if (wid == 0 && lane < 8) {
        int ws = wsum[lane];
        #pragma unroll
        for (int o = 1; o < 8; o <<= 1) {
            int y = __shfl_up_sync(0xffu, ws, o);
            if (lane >= o) ws += y;
        }
        wsum[lane] = ws;
    }
    __syncthreads();
    int incl = x + (wid ? wsum[wid - 1] : 0);
    if (i < N_NODES) g_off[i] = incl;
    if (t == 255) g_bsum[b] = incl;
}

__global__ void scan2_kernel() {
    __shared__ int wsum[8];
    int t = threadIdx.x, lane = t & 31, wid = t >> 5;
    int v = (t < NB) ? g_bsum[t] : 0;
    int x = v;
    #pragma unroll
    for (int o = 1; o < 32; o <<= 1) {
        int y = __shfl_up_sync(0xffffffffu, x, o);
        if (lane >= o) x += y;
    }
    if (lane == 31) wsum[wid] = x;
    __syncthreads();
    if (wid == 0 && lane < 8) {
        int ws = wsum[lane];
        #pragma unroll
        for (int o = 1; o < 8; o <<= 1) {
            int y = __shfl_up_sync(0xffu, ws, o);
            if (lane >= o) ws += y;
        }
        wsum[lane] = ws;
    }
    __syncthreads();
    int excl = x - v + (wid ? wsum[wid - 1] : 0);
    if (t < NB) g_boff[t] = excl;
}

__global__ void scan3_kernel() {
    int i = blockIdx.x * blockDim.x + threadIdx.x;
    if (i < N_NODES) {
        int e = g_off[i] - g_deg[i] + g_boff[blockIdx.x];
        g_off[i] = e;
        g_cur[i] = e;
    }
    if (i == 0) g_off[N_NODES] = EN;
}

__global__ void scatter_kernel(const void* __restrict__ ei) {
    int e = blockIdx.x * blockDim.x + threadIdx.x;
    if (e >= EN) return;
    int src, dst;
    if (e < N_EDGES) {
        int is64 = g_is64;
        src = load_edge(ei, is64, e);
        dst = load_edge(ei, is64, (size_t)N_EDGES + e);
    } else {
        src = e - N_EDGES; dst = src;
    }
    int pos = atomicAdd(&g_cur[dst], 1);
    g_csr_src[pos] = src;
}

// ================= fp16-split GEMM, cp.async pipeline, fused attdot ==========
// C[m][n] = sum_k A[m][k]*B[n][k]; A = Ah + Al (fp16), B = Bh (fp16 only).
// Per 32-fp32-k tile, A smem row (128B): [Ah k0..31 | Al k0..31];
// B smem row uses [0,64) = Bh k0..31. 4 k16 MMA steps/tile, 8 tiles.
#define GBM 128
#define GBN 128
#define GKF 32
#define SBUF 16384
#define GEMM_K 256

template <int LAYER>
__global__ __launch_bounds__(256, 2) void gemm_kernel(
    int M, int Nc,
    const float* __restrict__ att_s_full, const float* __restrict__ att_d_full)
{
    const __half* Ah = (LAYER == 1) ? g_xh  : g_o1h;
    const __half* Al = (LAYER == 1) ? g_xl  : g_o1l;
    const __half* Bh = (LAYER == 1) ? g_w1h : g_w2h;
    __half* Ch = (LAYER == 1) ? g_h1h : g_h2h;
    float* a_s = (LAYER == 1) ? g_as1 : g_as2;
    float* a_d = (LAYER == 1) ? g_ad1 : g_ad2;
    constexpr int H = (LAYER == 1) ? 2 : 1;

    __shared__ __align__(16) char sA[2 * SBUF];
    __shared__ __align__(16) char sB[2 * SBUF];
    uint32_t sAu = (uint32_t)__cvta_generic_to_shared(sA);
    uint32_t sBu = (uint32_t)__cvta_generic_to_shared(sB);

    const int tid = threadIdx.x;
    const int lane = tid & 31, wid = tid >> 5;
    const int wm = wid & 1, wn = wid >> 1;
    const int bm = blockIdx.x * GBM;
    const int bn = blockIdx.y * GBN;

    float acc[4][4][4];
    #pragma unroll
    for (int i = 0; i < 4; i++)
        #pragma unroll
        for (int j = 0; j < 4; j++)
            #pragma unroll
            for (int r = 0; r < 4; r++) acc[i][j][r] = 0.f;

    const int crow = tid >> 1;
    const int chalf = tid & 1;

    auto issue_tile = [&](int kt) {
        uint32_t bo = (uint32_t)(kt & 1) * SBUF;
        int k0 = kt * GKF;                          // fp32-k == fp16 col index
        uint32_t rb = (uint32_t)crow * 128;
        uint32_t co = (uint32_t)chalf * 32;
        {
            int grow = bm + crow;
            int sz = (grow < M) ? 16 : 0;
            const char* ph = (const char*)(Ah + (size_t)grow * GEMM_K + k0) + co;
            const char* pl = (const char*)(Al + (size_t)grow * GEMM_K + k0) + co;
            cp16(sAu + bo + swz(rb + co),           ph,      sz);
            cp16(sAu + bo + swz(rb + co + 16),      ph + 16, sz);
            cp16(sAu + bo + swz(rb + 64 + co),      pl,      sz);
            cp16(sAu + bo + swz(rb + 64 + co + 16), pl + 16, sz);
        }
        {
            int gbrow = bn + crow;
            const char* pb = (const char*)(Bh + (size_t)gbrow * GEMM_K + k0) + co;
            cp16(sBu + bo + swz(rb + co),      pb,      16);
            cp16(sBu + bo + swz(rb + co + 16), pb + 16, 16);
        }
    };

    const int la_r   = lane & 7;
    const int la_sub = lane >> 3;
    const int lb_sub = (lane >> 3) & 1;

    const int nktiles = GEMM_K / GKF;   // 8
    issue_tile(0); cp_commit();
    issue_tile(1); cp_commit();

    for (int kt = 0; kt < nktiles; kt++) {
        cp_wait1();
        __syncthreads();
        uint32_t bo = (uint32_t)(kt & 1) * SBUF;
        #pragma unroll
        for (int ks = 0; ks < 4; ks++) {
            uint32_t a[4][4], b[4][2];
            #pragma unroll
            for (int mt = 0; mt < 4; mt++) {
                int row = wm * 64 + mt * 16 + la_r + (la_sub & 1) * 8;
                uint32_t cb = (uint32_t)ks * 32 + (la_sub >> 1) * 16;
                uint32_t ad = sAu + bo + swz((uint32_t)row * 128 + cb);
                asm volatile("ldmatrix.sync.aligned.m8n8.x4.shared.b16 {%0,%1,%2,%3}, [%4];"
                             : "=r"(a[mt][0]), "=r"(a[mt][1]), "=r"(a[mt][2]), "=r"(a[mt][3])
                             : "r"(ad));
            }
            #pragma unroll
            for (int nt = 0; nt < 4; nt++) {
                int row = wn * 32 + nt * 8 + la_r;
                uint32_t cb = (uint32_t)(ks & 1) * 32 + lb_sub * 16;
                uint32_t ad = sBu + bo + swz((uint32_t)row * 128 + cb);
                asm volatile("ldmatrix.sync.aligned.m8n8.x2.shared.b16 {%0,%1}, [%2];"
                             : "=r"(b[nt][0]), "=r"(b[nt][1])
                             : "r"(ad));
            }
            #pragma unroll
            for (int mt = 0; mt < 4; mt++)
                #pragma unroll
                for (int nt = 0; nt < 4; nt++)
                    mma_fp16(acc[mt][nt][0], acc[mt][nt][1], acc[mt][nt][2], acc[mt][nt][3],
                             a[mt][0], a[mt][1], a[mt][2], a[mt][3], b[nt][0], b[nt][1]);
        }
        __syncthreads();
        if (kt + 2 < nktiles) issue_tile(kt + 2);
        cp_commit();
    }

    // ---- epilogue: fp16 C + fused attention dots ----
    const int g = lane >> 2, tg = lane & 3;

    #pragma unroll
    for (int mt = 0; mt < 4; mt++) {
        int r0 = bm + wm * 64 + mt * 16 + g;
        int r1 = r0 + 8;
        #pragma unroll
        for (int nt = 0; nt < 4; nt++) {
            int col = bn + wn * 32 + nt * 8 + tg * 2;
            if (r0 < M)
                *(__half2*)&Ch[(size_t)r0 * Nc + col] =
                    __floats2half2_rn(acc[mt][nt][0], acc[mt][nt][1]);
            if (r1 < M)
                *(__half2*)&Ch[(size_t)r1 * Nc + col] =
                    __floats2half2_rn(acc[mt][nt][2], acc[mt][nt][3]);
        }
    }

    float2 asv[4], adv[4];
    #pragma unroll
    for (int nt = 0; nt < 4; nt++) {
        int col = bn + wn * 32 + nt * 8 + tg * 2;
        asv[nt] = *(const float2*)&att_s_full[col];
        adv[nt] = *(const float2*)&att_d_full[col];
    }
    float ssr0[4], ssr1[4], sdr0[4], sdr1[4];
    #pragma unroll
    for (int mt = 0; mt < 4; mt++) {
        float s0 = 0.f, s1 = 0.f, d0 = 0.f, d1 = 0.f;
        #pragma unroll
        for (int nt = 0; nt < 4; nt++) {
            s0 += asv[nt].x * acc[mt][nt][0] + asv[nt].y * acc[mt][nt][1];
            s1 += asv[nt].x * acc[mt][nt][2] + asv[nt].y * acc[mt][nt][3];
            d0 += adv[nt].x * acc[mt][nt][0] + adv[nt].y * acc[mt][nt][1];
            d1 += adv[nt].x * acc[mt][nt][2] + adv[nt].y * acc[mt][nt][3];
        }
        #pragma unroll
        for (int o = 1; o <= 2; o <<= 1) {
            s0 += __shfl_xor_sync(0xffffffffu, s0, o);
            s1 += __shfl_xor_sync(0xffffffffu, s1, o);
            d0 += __shfl_xor_sync(0xffffffffu, d0, o);
            d1 += __shfl_xor_sync(0xffffffffu, d1, o);
        }
        ssr0[mt] = s0; ssr1[mt] = s1; sdr0[mt] = d0; sdr1[mt] = d1;
    }
    __syncthreads();
    float* red = (float*)sA;
    if (tg == 0) {
        #pragma unroll
        for (int mt = 0; mt < 4; mt++) {
            int rl0 = wm * 64 + mt * 16 + g;
            red[wn * 128 + rl0]           = ssr0[mt];
            red[wn * 128 + rl0 + 8]       = ssr1[mt];
            red[512 + wn * 128 + rl0]     = sdr0[mt];
            red[512 + wn * 128 + rl0 + 8] = sdr1[mt];
        }
    }
    __syncthreads();
    if (tid < 128) {
        int row = tid;
        float ss = red[row] + red[128 + row] + red[256 + row] + red[384 + row];
        float sd = red[512 + row] + red[640 + row] + red[768 + row] + red[896 + row];
        int grow = bm + row;
        if (grow < M) {
            int head = (H == 2) ? (int)blockIdx.y : 0;
            a_s[grow * H + head] = ss;
            a_d[grow * H + head] = sd;
        }
    }
}

// ---- fused aggregation: softmax weights computed in-block, one pass --------
// out[n] = (sum_j e_j * v_j) / (sum_j e_j) + bias,  e_j = exp(leaky(a_s+a_d)).
template <int LAYER, int H, int C>
__global__ void aggregate_kernel(const float* __restrict__ bias,
                                 float* __restrict__ out_param)
{
    constexpr int HC = H * C;
    constexpr int CH = HC / 2;    // == blockDim
    const __half* hfeat = (LAYER == 1) ? g_h1h : g_h2h;
    const float* a_s    = (LAYER == 1) ? g_as1 : g_as2;
    const float* a_d    = (LAYER == 1) ? g_ad1 : g_ad2;

    __shared__ int   s_src[CH];
    __shared__ float s_e[H * CH];

    int n = blockIdx.x;
    int t = threadIdx.x;
    int f = 2 * t;
    int head = f / C;
    int s0 = g_off[n], s1 = g_off[n + 1];

    float adv[H];
    #pragma unroll
    for (int h = 0; h < H; h++) adv[h] = a_d[n * H + h];

    float ax = 0.f, ay = 0.f, wsum = 0.f;

    for (int j0 = s0; j0 < s1; j0 += CH) {
        int cnt = min(CH, s1 - j0);
        if (t < cnt) {
            int src = g_csr_src[j0 + t];
            s_src[t] = src;
            #pragma unroll
            for (int h = 0; h < H; h++) {
                float l = a_s[src * H + h] + adv[h];
                l = l > 0.f ? l : 0.2f * l;
                s_e[h * CH + t] = __expf(l);
            }
        }
        __syncthreads();
        const float* eh = &s_e[head * CH];
        int i = 0;
        for (; i + 3 < cnt; i += 4) {
            int sr0 = s_src[i], sr1 = s_src[i + 1], sr2 = s_src[i + 2], sr3 = s_src[i + 3];
            float e0 = eh[i], e1 = eh[i + 1], e2 = eh[i + 2], e3 = eh[i + 3];
            float2 v0 = __half22float2(*(const __half2*)&hfeat[(size_t)sr0 * HC + f]);
            float2 v1 = __half22float2(*(const __half2*)&hfeat[(size_t)sr1 * HC + f]);
            float2 v2 = __half22float2(*(const __half2*)&hfeat[(size_t)sr2 * HC + f]);
            float2 v3 = __half22float2(*(const __half2*)&hfeat[(size_t)sr3 * HC + f]);
            ax += e0 * v0.x + e1 * v1.x + e2 * v2.x + e3 * v3.x;
            ay += e0 * v0.y + e1 * v1.y + e2 * v2.y + e3 * v3.y;
            wsum += (e0 + e1) + (e2 + e3);
        }
        for (; i < cnt; i++) {
            int sr = s_src[i];
            float e = eh[i];
            float2 v = __half22float2(*(const __half2*)&hfeat[(size_t)sr * HC + f]);
            ax += e * v.x;
            ay += e * v.y;
            wsum += e;
        }
        __syncthreads();
    }

    float iv = 1.f / wsum;
    float ox = ax * iv + bias[f];
    float oy = ay * iv + bias[f + 1];
    if (LAYER == 1) {
        ox = ox > 0.f ? ox : 0.f;
        oy = oy > 0.f ? oy : 0.f;
        __half hx = __float2half_rn(ox), hy = __float2half_rn(oy);
        __half lx = __float2half_rn(ox - __half2float(hx));
        __half ly = __float2half_rn(oy - __half2float(hy));
        __half2 hv(hx, hy), lv(lx, ly);
        *(__half2*)&g_o1h[(size_t)n * HC + f] = hv;
        *(__half2*)&g_o1l[(size_t)n * HC + f] = lv;
    } else {
        *(float2*)&out_param[(size_t)n * HC + f] = make_float2(ox, oy);
    }
}

// ---------------- launch ----------------
extern "C" void kernel_launch(void* const* d_in, const int* in_sizes, int n_in,
                              void* d_out, int out_size)
{
    const float* x   = (const float*)d_in[0];
    const void*  ei  = d_in[1];
    const float* W1  = (const float*)d_in[2];
    const float* as1 = (const float*)d_in[3];
    const float* ad1 = (const float*)d_in[4];
    const float* b1  = (const float*)d_in[5];
    const float* W2  = (const float*)d_in[6];
    const float* as2 = (const float*)d_in[7];
    const float* ad2 = (const float*)d_in[8];
    const float* b2  = (const float*)d_in[9];
    float* out = (float*)d_out;

    // operand splits
    split_x_kernel<<<(N_NODES * 256 / 4 + 255) / 256, 256>>>(x);
    split_w_kernel<<<((256 * 256 + 128 * 256) / 4 + 255) / 256, 256>>>(W1, W2);

    // CSR build
    init_kernel<<<NB, 256>>>((const int*)ei);
    hist_kernel<<<(N_EDGES + 255) / 256, 256>>>(ei);
    scan1_kernel<<<NB, 256>>>();
    scan2_kernel<<<1, 256>>>();
    scan3_kernel<<<NB, 256>>>();
    scatter_kernel<<<(EN + 255) / 256, 256>>>(ei);

    // Layer 1
    gemm_kernel<1><<<dim3((N_NODES + 127) / 128, 2), 256>>>(N_NODES, 256, as1, ad1);
    aggregate_kernel<1, 2, 128><<<N_NODES, 128>>>(b1, nullptr);

    // Layer 2
    gemm_kernel<2><<<dim3((N_NODES + 127) / 128, 1), 256>>>(N_NODES, 128, as2, ad2);
    aggregate_kernel<2, 1, 128><<<N_NODES, 64>>>(b2, out);
}

// round 10
// speedup vs baseline: 2.7197x; 1.1850x over previous
#include <cuda_runtime.h>
#include <cuda_fp16.h>
#include <cstdint>

#define N_NODES 50000
#define N_EDGES 800000
#define EN      (N_EDGES + N_NODES)
#define NB      ((N_NODES + 255) / 256)

// ---------------- scratch (device globals; no allocation) ----------------
__device__ __half g_xh[(size_t)N_NODES * 256];   // x fp16
__device__ __half g_w1h[256 * 256];              // W1 fp16
__device__ __half g_w2h[128 * 256];              // W2 fp16
__device__ __half g_o1h[(size_t)N_NODES * 256];  // layer1 GAT out fp16
__device__ __half g_h1h[(size_t)N_NODES * 256];  // layer1 linear out fp16
__device__ __half g_h2h[(size_t)N_NODES * 128];  // layer2 linear out fp16
__device__ float  g_as1[N_NODES * 2];
__device__ float  g_ad1[N_NODES * 2];
__device__ float  g_as2[N_NODES];
__device__ float  g_ad2[N_NODES];
__device__ int    g_deg[N_NODES + 8];
__device__ int    g_off[N_NODES + 8];
__device__ int    g_cur[N_NODES + 8];
__device__ int    g_csr_src[EN];
__device__ int    g_is64;
__device__ int    g_bsum[NB + 8];
__device__ int    g_boff[NB + 8];

// ---------------- helpers ----------------
__device__ __forceinline__ uint32_t swz(uint32_t b) { return b ^ ((b >> 3) & 0x70); }

__device__ __forceinline__ uint32_t pack_h2(__half a, __half b) {
    __half2 t(a, b);
    return *reinterpret_cast<uint32_t*>(&t);
}

__device__ __forceinline__ void cp16(uint32_t dst, const void* src, int sz) {
    asm volatile("cp.async.cg.shared.global [%0], [%1], 16, %2;\n"
                 :: "r"(dst), "l"(src), "r"(sz) : "memory");
}
__device__ __forceinline__ void cp_commit() {
    asm volatile("cp.async.commit_group;\n" ::: "memory");
}
__device__ __forceinline__ void cp_wait1() {
    asm volatile("cp.async.wait_group 1;\n" ::: "memory");
}

__device__ __forceinline__ void mma_fp16(float& c0, float& c1, float& c2, float& c3,
                                         uint32_t a0, uint32_t a1, uint32_t a2, uint32_t a3,
                                         uint32_t b0, uint32_t b1) {
    asm volatile(
        "mma.sync.aligned.m16n8k16.row.col.f32.f16.f16.f32 "
        "{%0,%1,%2,%3}, {%4,%5,%6,%7}, {%8,%9}, {%0,%1,%2,%3};\n"
        : "+f"(c0), "+f"(c1), "+f"(c2), "+f"(c3)
        : "r"(a0), "r"(a1), "r"(a2), "r"(a3), "r"(b0), "r"(b1));
}

__device__ __forceinline__ uint2 cvt4h(float4 v) {
    return make_uint2(pack_h2(__float2half_rn(v.x), __float2half_rn(v.y)),
                      pack_h2(__float2half_rn(v.z), __float2half_rn(v.w)));
}

// ---------------- operand convert + deg init + dtype detect ----------------
__global__ void split_x_kernel(const float* __restrict__ src,
                               const int* __restrict__ ei_w) {
    int i = blockIdx.x * blockDim.x + threadIdx.x;
    const int n4 = N_NODES * 256 / 4;
    if (blockIdx.x == 0) {
        if (threadIdx.x == 0) g_is64 = 1;
        __syncthreads();
        if (ei_w[2 * threadIdx.x + 1] != 0) atomicAnd(&g_is64, 0);
    }
    if (i < N_NODES) g_deg[i] = 1;   // self loop count
    if (i >= n4) return;
    ((uint2*)g_xh)[i] = cvt4h(((const float4*)src)[i]);
}

__global__ void split_w_kernel(const float* __restrict__ W1src,
                               const float* __restrict__ W2src) {
    int i = blockIdx.x * blockDim.x + threadIdx.x;
    const int n1 = 256 * 256 / 4;
    const int n2 = 128 * 256 / 4;
    if (i < n1) {
        ((uint2*)g_w1h)[i] = cvt4h(((const float4*)W1src)[i]);
    } else if (i < n1 + n2) {
        int idx = i - n1;
        ((uint2*)g_w2h)[idx] = cvt4h(((const float4*)W2src)[idx]);
    }
}

// ---------------- CSR build ----------------
__device__ __forceinline__ int load_edge(const void* ei, int is64, size_t idx) {
    if (is64) return (int)((const long long*)ei)[idx];
    return ((const int*)ei)[idx];
}

__global__ void hist_kernel(const void* __restrict__ ei) {
    int e = blockIdx.x * blockDim.x + threadIdx.x;
    if (e < N_EDGES) {
        int dst = load_edge(ei, g_is64, (size_t)N_EDGES + e);
        atomicAdd(&g_deg[dst], 1);
    }
}

__global__ void scan1_kernel() {
    __shared__ int wsum[8];
    int b = blockIdx.x, t = threadIdx.x, lane = t & 31, wid = t >> 5;
    int i = b * 256 + t;
    int v = (i < N_NODES) ? g_deg[i] : 0;
    int x = v;
    #pragma unroll
    for (int o = 1; o < 32; o <<= 1) {
        int y = __shfl_up_sync(0xffffffffu, x, o);
        if (lane >= o) x += y;
    }
    if (lane == 31) wsum[wid] = x;
    __syncthreads();
    if (wid == 0 && lane < 8) {
        int ws = wsum[lane];
        #pragma unroll
        for (int o = 1; o < 8; o <<= 1) {
            int y = __shfl_up_sync(0xffu, ws, o);
            if (lane >= o) ws += y;
        }
        wsum[lane] = ws;
    }
    __syncthreads();
    int incl = x + (wid ? wsum[wid - 1] : 0);
    if (i < N_NODES) g_off[i] = incl;
    if (t == 255) g_bsum[b] = incl;
}

__global__ void scan2_kernel() {
    __shared__ int wsum[8];
    int t = threadIdx.x, lane = t & 31, wid = t >> 5;
    int v = (t < NB) ? g_bsum[t] : 0;
    int x = v;
    #pragma unroll
    for (int o = 1; o < 32; o <<= 1) {
        int y = __shfl_up_sync(0xffffffffu, x, o);
        if (lane >= o) x += y;
    }
    if (lane == 31) wsum[wid] = x;
    __syncthreads();
    if (wid == 0 && lane < 8) {
        int ws = wsum[lane];
        #pragma unroll
        for (int o = 1; o < 8; o <<= 1) {
            int y = __shfl_up_sync(0xffu, ws, o);
            if (lane >= o) ws += y;
        }
        wsum[lane] = ws;
    }
    __syncthreads();
    int excl = x - v + (wid ? wsum[wid - 1] : 0);
    if (t < NB) g_boff[t] = excl;
}

__global__ void scan3_kernel() {
    int i = blockIdx.x * blockDim.x + threadIdx.x;
    if (i < N_NODES) {
        int e = g_off[i] - g_deg[i] + g_boff[blockIdx.x];
        g_off[i] = e;
        g_cur[i] = e;
    }
    if (i == 0) g_off[N_NODES] = EN;
}

__global__ void scatter_kernel(const void* __restrict__ ei) {
    int e = blockIdx.x * blockDim.x + threadIdx.x;
    if (e >= EN) return;
    int src, dst;
    if (e < N_EDGES) {
        int is64 = g_is64;
        src = load_edge(ei, is64, e);
        dst = load_edge(ei, is64, (size_t)N_EDGES + e);
    } else {
        src = e - N_EDGES; dst = src;
    }
    int pos = atomicAdd(&g_cur[dst], 1);
    g_csr_src[pos] = src;
}

// ================= fp16 GEMM, cp.async pipeline, fused attdot ================
// C[m][n] = sum_k A[m][k]*B[n][k]; A,B fp16. K-chunk = 64 fp16 cols (128B row).
#define GBM 128
#define GBN 128
#define GKF 64
#define SBUF 16384
#define GEMM_K 256

template <int LAYER>
__global__ __launch_bounds__(256, 2) void gemm_kernel(
    int M, int Nc,
    const float* __restrict__ att_s_full, const float* __restrict__ att_d_full)
{
    const __half* Ah = (LAYER == 1) ? g_xh  : g_o1h;
    const __half* Bh = (LAYER == 1) ? g_w1h : g_w2h;
    __half* Ch = (LAYER == 1) ? g_h1h : g_h2h;
    float* a_s = (LAYER == 1) ? g_as1 : g_as2;
    float* a_d = (LAYER == 1) ? g_ad1 : g_ad2;
    constexpr int H = (LAYER == 1) ? 2 : 1;

    __shared__ __align__(16) char sA[2 * SBUF];
    __shared__ __align__(16) char sB[2 * SBUF];
    uint32_t sAu = (uint32_t)__cvta_generic_to_shared(sA);
    uint32_t sBu = (uint32_t)__cvta_generic_to_shared(sB);

    const int tid = threadIdx.x;
    const int lane = tid & 31, wid = tid >> 5;
    const int wm = wid & 1, wn = wid >> 1;
    const int bm = blockIdx.x * GBM;
    const int bn = blockIdx.y * GBN;

    float acc[4][4][4];
    #pragma unroll
    for (int i = 0; i < 4; i++)
        #pragma unroll
        for (int j = 0; j < 4; j++)
            #pragma unroll
            for (int r = 0; r < 4; r++) acc[i][j][r] = 0.f;

    const int crow = tid >> 1;        // 0..127
    const int chalf = tid & 1;        // 64B half of the 128B row

    auto issue_tile = [&](int kt) {
        uint32_t bo = (uint32_t)(kt & 1) * SBUF;
        int k0 = kt * GKF;
        uint32_t rb = (uint32_t)crow * 128;
        uint32_t co = (uint32_t)chalf * 64;
        {
            int grow = bm + crow;
            int sz = (grow < M) ? 16 : 0;
            const char* pa = (const char*)(Ah + (size_t)grow * GEMM_K + k0) + co;
            #pragma unroll
            for (int s = 0; s < 4; s++)
                cp16(sAu + bo + swz(rb + co + s * 16), pa + s * 16, sz);
        }
        {
            int gbrow = bn + crow;
            const char* pb = (const char*)(Bh + (size_t)gbrow * GEMM_K + k0) + co;
            #pragma unroll
            for (int s = 0; s < 4; s++)
                cp16(sBu + bo + swz(rb + co + s * 16), pb + s * 16, 16);
        }
    };

    const int la_r   = lane & 7;
    const int la_sub = lane >> 3;
    const int lb_sub = (lane >> 3) & 1;

    const int nktiles = GEMM_K / GKF;   // 4
    issue_tile(0); cp_commit();
    issue_tile(1); cp_commit();

    for (int kt = 0; kt < nktiles; kt++) {
        cp_wait1();
        __syncthreads();
        uint32_t bo = (uint32_t)(kt & 1) * SBUF;
        #pragma unroll
        for (int ks = 0; ks < 4; ks++) {
            uint32_t a[4][4], b[4][2];
            #pragma unroll
            for (int mt = 0; mt < 4; mt++) {
                int row = wm * 64 + mt * 16 + la_r + (la_sub & 1) * 8;
                uint32_t cb = (uint32_t)ks * 32 + (la_sub >> 1) * 16;
                uint32_t ad = sAu + bo + swz((uint32_t)row * 128 + cb);
                asm volatile("ldmatrix.sync.aligned.m8n8.x4.shared.b16 {%0,%1,%2,%3}, [%4];"
                             : "=r"(a[mt][0]), "=r"(a[mt][1]), "=r"(a[mt][2]), "=r"(a[mt][3])
                             : "r"(ad));
            }
            #pragma unroll
            for (int nt = 0; nt < 4; nt++) {
                int row = wn * 32 + nt * 8 + la_r;
                uint32_t cb = (uint32_t)ks * 32 + lb_sub * 16;
                uint32_t ad = sBu + bo + swz((uint32_t)row * 128 + cb);
                asm volatile("ldmatrix.sync.aligned.m8n8.x2.shared.b16 {%0,%1}, [%2];"
                             : "=r"(b[nt][0]), "=r"(b[nt][1])
                             : "r"(ad));
            }
            #pragma unroll
            for (int mt = 0; mt < 4; mt++)
                #pragma unroll
                for (int nt = 0; nt < 4; nt++)
                    mma_fp16(acc[mt][nt][0], acc[mt][nt][1], acc[mt][nt][2], acc[mt][nt][3],
                             a[mt][0], a[mt][1], a[mt][2], a[mt][3], b[nt][0], b[nt][1]);
        }
        __syncthreads();
        if (kt + 2 < nktiles) issue_tile(kt + 2);
        cp_commit();
    }

    // ---- epilogue: fp16 C + fused attention dots ----
    const int g = lane >> 2, tg = lane & 3;

    #pragma unroll
    for (int mt = 0; mt < 4; mt++) {
        int r0 = bm + wm * 64 + mt * 16 + g;
        int r1 = r0 + 8;
        #pragma unroll
        for (int nt = 0; nt < 4; nt++) {
            int col = bn + wn * 32 + nt * 8 + tg * 2;
            if (r0 < M)
                *(__half2*)&Ch[(size_t)r0 * Nc + col] =
                    __floats2half2_rn(acc[mt][nt][0], acc[mt][nt][1]);
            if (r1 < M)
                *(__half2*)&Ch[(size_t)r1 * Nc + col] =
                    __floats2half2_rn(acc[mt][nt][2], acc[mt][nt][3]);
        }
    }

    float2 asv[4], adv[4];
    #pragma unroll
    for (int nt = 0; nt < 4; nt++) {
        int col = bn + wn * 32 + nt * 8 + tg * 2;
        asv[nt] = *(const float2*)&att_s_full[col];
        adv[nt] = *(const float2*)&att_d_full[col];
    }
    float ssr0[4], ssr1[4], sdr0[4], sdr1[4];
    #pragma unroll
    for (int mt = 0; mt < 4; mt++) {
        float s0 = 0.f, s1 = 0.f, d0 = 0.f, d1 = 0.f;
        #pragma unroll
        for (int nt = 0; nt < 4; nt++) {
            s0 += asv[nt].x * acc[mt][nt][0] + asv[nt].y * acc[mt][nt][1];
            s1 += asv[nt].x * acc[mt][nt][2] + asv[nt].y * acc[mt][nt][3];
            d0 += adv[nt].x * acc[mt][nt][0] + adv[nt].y * acc[mt][nt][1];
            d1 += adv[nt].x * acc[mt][nt][2] + adv[nt].y * acc[mt][nt][3];
        }
        #pragma unroll
        for (int o = 1; o <= 2; o <<= 1) {
            s0 += __shfl_xor_sync(0xffffffffu, s0, o);
            s1 += __shfl_xor_sync(0xffffffffu, s1, o);
            d0 += __shfl_xor_sync(0xffffffffu, d0, o);
            d1 += __shfl_xor_sync(0xffffffffu, d1, o);
        }
        ssr0[mt] = s0; ssr1[mt] = s1; sdr0[mt] = d0; sdr1[mt] = d1;
    }
    __syncthreads();
    float* red = (float*)sA;
    if (tg == 0) {
        #pragma unroll
        for (int mt = 0; mt < 4; mt++) {
            int rl0 = wm * 64 + mt * 16 + g;
            red[wn * 128 + rl0]           = ssr0[mt];
            red[wn * 128 + rl0 + 8]       = ssr1[mt];
            red[512 + wn * 128 + rl0]     = sdr0[mt];
            red[512 + wn * 128 + rl0 + 8] = sdr1[mt];
        }
    }
    __syncthreads();
    if (tid < 128) {
        int row = tid;
        float ss = red[row] + red[128 + row] + red[256 + row] + red[384 + row];
        float sd = red[512 + row] + red[640 + row] + red[768 + row] + red[896 + row];
        int grow = bm + row;
        if (grow < M) {
            int head = (H == 2) ? (int)blockIdx.y : 0;
            a_s[grow * H + head] = ss;
            a_d[grow * H + head] = sd;
        }
    }
}

// ---- fused aggregation: softmax weights computed in-block, one pass --------
template <int LAYER, int H, int C>
__global__ void aggregate_kernel(const float* __restrict__ bias,
                                 float* __restrict__ out_param)
{
    constexpr int HC = H * C;
    constexpr int CH = HC / 2;    // == blockDim
    const __half* hfeat = (LAYER == 1) ? g_h1h : g_h2h;
    const float* a_s    = (LAYER == 1) ? g_as1 : g_as2;
    const float* a_d    = (LAYER == 1) ? g_ad1 : g_ad2;

    __shared__ int   s_src[CH];
    __shared__ float s_e[H * CH];

    int n = blockIdx.x;
    int t = threadIdx.x;
    int f = 2 * t;
    int head = f / C;
    int s0 = g_off[n], s1 = g_off[n + 1];

    float adv[H];
    #pragma unroll
    for (int h = 0; h < H; h++) adv[h] = a_d[n * H + h];

    float ax = 0.f, ay = 0.f, wsum = 0.f;

    for (int j0 = s0; j0 < s1; j0 += CH) {
        int cnt = min(CH, s1 - j0);
        if (t < cnt) {
            int src = g_csr_src[j0 + t];
            s_src[t] = src;
            #pragma unroll
            for (int h = 0; h < H; h++) {
                float l = a_s[src * H + h] + adv[h];
                l = l > 0.f ? l : 0.2f * l;
                s_e[h * CH + t] = __expf(l);
            }
        }
        __syncthreads();
        const float* eh = &s_e[head * CH];
        int i = 0;
        for (; i + 3 < cnt; i += 4) {
            int sr0 = s_src[i], sr1 = s_src[i + 1], sr2 = s_src[i + 2], sr3 = s_src[i + 3];
            float e0 = eh[i], e1 = eh[i + 1], e2 = eh[i + 2], e3 = eh[i + 3];
            float2 v0 = __half22float2(*(const __half2*)&hfeat[(size_t)sr0 * HC + f]);
            float2 v1 = __half22float2(*(const __half2*)&hfeat[(size_t)sr1 * HC + f]);
            float2 v2 = __half22float2(*(const __half2*)&hfeat[(size_t)sr2 * HC + f]);
            float2 v3 = __half22float2(*(const __half2*)&hfeat[(size_t)sr3 * HC + f]);
            ax += e0 * v0.x + e1 * v1.x + e2 * v2.x + e3 * v3.x;
            ay += e0 * v0.y + e1 * v1.y + e2 * v2.y + e3 * v3.y;
            wsum += (e0 + e1) + (e2 + e3);
        }
        for (; i < cnt; i++) {
            int sr = s_src[i];
            float e = eh[i];
            float2 v = __half22float2(*(const __half2*)&hfeat[(size_t)sr * HC + f]);
            ax += e * v.x;
            ay += e * v.y;
            wsum += e;
        }
        __syncthreads();
    }

    float iv = 1.f / wsum;
    float ox = ax * iv + bias[f];
    float oy = ay * iv + bias[f + 1];
    if (LAYER == 1) {
        ox = ox > 0.f ? ox : 0.f;
        oy = oy > 0.f ? oy : 0.f;
        *(__half2*)&g_o1h[(size_t)n * HC + f] = __floats2half2_rn(ox, oy);
    } else {
        *(float2*)&out_param[(size_t)n * HC + f] = make_float2(ox, oy);
    }
}

// ---------------- launch ----------------
extern "C" void kernel_launch(void* const* d_in, const int* in_sizes, int n_in,
                              void* d_out, int out_size)
{
    const float* x   = (const float*)d_in[0];
    const void*  ei  = d_in[1];
    const float* W1  = (const float*)d_in[2];
    const float* as1 = (const float*)d_in[3];
    const float* ad1 = (const float*)d_in[4];
    const float* b1  = (const float*)d_in[5];
    const float* W2  = (const float*)d_in[6];
    const float* as2 = (const float*)d_in[7];
    const float* ad2 = (const float*)d_in[8];
    const float* b2  = (const float*)d_in[9];
    float* out = (float*)d_out;

    // convert operands + init deg + detect edge dtype (one kernel)
    split_x_kernel<<<(N_NODES * 256 / 4 + 255) / 256, 256>>>(x, (const int*)ei);
    split_w_kernel<<<((256 * 256 + 128 * 256) / 4 + 255) / 256, 256>>>(W1, W2);

    // CSR build
    hist_kernel<<<(N_EDGES + 255) / 256, 256>>>(ei);
    scan1_kernel<<<NB, 256>>>();
    scan2_kernel<<<1, 256>>>();
    scan3_kernel<<<NB, 256>>>();
    scatter_kernel<<<(EN + 255) / 256, 256>>>(ei);

    // Layer 1
    gemm_kernel<1><<<dim3((N_NODES + 127) / 128, 2), 256>>>(N_NODES, 256, as1, ad1);
    aggregate_kernel<1, 2, 128><<<N_NODES, 128>>>(b1, nullptr);

    // Layer 2
    gemm_kernel<2><<<dim3((N_NODES + 127) / 128, 1), 256>>>(N_NODES, 128, as2, ad2);
    aggregate_kernel<2, 1, 128><<<N_NODES, 64>>>(b2, out);
}